// round 7
// baseline (speedup 1.0000x reference)
#include <cuda_runtime.h>
#include <stdint.h>

#define N_MAX 100000
#define E_MAX 1600000

// ---------------- scratch (device globals; no allocation) ----------------
__device__ float g_h0[N_MAX * 128];
__device__ float g_h1[N_MAX * 128];
__device__ float g_t1[N_MAX * 128];
__device__ float g_t2[N_MAX * 64];
__device__ float g_dis[N_MAX];
__device__ float g_wn[E_MAX];
__device__ int   g_hist[N_MAX];
__device__ int   g_rowptr[N_MAX + 1];
__device__ int   g_cursor[N_MAX];
__device__ int   g_esrc[E_MAX];
__device__ int   g_is64;

// scratch buffer ids (resolved device-side; no cudaGetSymbolAddress anywhere)
__device__ __forceinline__ float* bufp(int id) {
  switch (id) {
    case 0: return g_h0;
    case 1: return g_h1;
    case 2: return g_t1;
    default: return g_t2;
  }
}

// ---------------- threefry2x32 (JAX-compatible) ----------------
__host__ __device__ static inline uint32_t rotl32(uint32_t v, int d) {
  return (v << d) | (v >> (32 - d));
}

__host__ __device__ static inline void threefry2x32(uint32_t k0, uint32_t k1,
                                                    uint32_t x0, uint32_t x1,
                                                    uint32_t& o0, uint32_t& o1) {
  uint32_t ks2 = k0 ^ k1 ^ 0x1BD11BDAu;
  x0 += k0; x1 += k1;
#define TF_R(r) { x0 += x1; x1 = rotl32(x1, (r)); x1 ^= x0; }
  TF_R(13) TF_R(15) TF_R(26) TF_R(6)
  x0 += k1; x1 += ks2 + 1u;
  TF_R(17) TF_R(29) TF_R(16) TF_R(24)
  x0 += ks2; x1 += k0 + 2u;
  TF_R(13) TF_R(15) TF_R(26) TF_R(6)
  x0 += k0; x1 += k1 + 3u;
  TF_R(17) TF_R(29) TF_R(16) TF_R(24)
  x0 += k1; x1 += ks2 + 4u;
  TF_R(13) TF_R(15) TF_R(26) TF_R(6)
  x0 += ks2; x1 += k0 + 5u;
#undef TF_R
  o0 = x0; o1 = x1;
}

// ---------------- edge dtype detection ----------------
// int64 little-endian: words are [lo0, hi0, lo1, hi1, ...]; hi words all 0
// (node ids < 2^31). int32: odd words are live node ids (P(64 zeros) ~ 0).
__global__ void detect_kernel(const uint32_t* __restrict__ eiw) {
  int all0 = 1;
  for (int i = 0; i < 64; i++)
    if (eiw[2 * i + 1] != 0u) { all0 = 0; break; }
  g_is64 = all0;
}

__device__ __forceinline__ int edge_val(const void* ei, int nE, int idx) {
  if (g_is64) return (int)((const long long*)ei)[idx];
  return ((const int*)ei)[idx];
}

// ---------------- graph preprocessing ----------------
__global__ void zero_hist_kernel(int n) {
  int i = blockIdx.x * blockDim.x + threadIdx.x;
  if (i < n) g_hist[i] = 0;
}

__global__ void hist_kernel(const void* __restrict__ ei, int nE, int n) {
  int e = blockIdx.x * blockDim.x + threadIdx.x;
  if (e < nE) {
    int c = edge_val(ei, nE, nE + e);  // col
    if ((unsigned)c < (unsigned)n) atomicAdd(&g_hist[c], 1);
  }
}

__global__ void dis_kernel(int n) {
  int i = blockIdx.x * blockDim.x + threadIdx.x;
  if (i < n) {
    int d = g_hist[i];
    g_dis[i] = (d > 0) ? rsqrtf((float)d) : 0.0f;
  }
}

// single-block exclusive scan over n counts -> rowptr[0..n], cursor copy
__global__ void scan_kernel(int n) {
  __shared__ int buf[1024];
  __shared__ int carry_s;
  int tid = threadIdx.x;
  if (tid == 0) carry_s = 0;
  __syncthreads();
  for (int base = 0; base < n; base += 1024) {
    int v = (base + tid < n) ? g_hist[base + tid] : 0;
    buf[tid] = v;
    __syncthreads();
    for (int off = 1; off < 1024; off <<= 1) {
      int t = (tid >= off) ? buf[tid - off] : 0;
      __syncthreads();
      buf[tid] += t;
      __syncthreads();
    }
    int carry = carry_s;
    int excl = carry + buf[tid] - v;
    if (base + tid < n) { g_rowptr[base + tid] = excl; g_cursor[base + tid] = excl; }
    __syncthreads();
    if (tid == 0) carry_s = carry + buf[1023];
    __syncthreads();
  }
  if (tid == 0) g_rowptr[n] = carry_s;
}

__global__ void scatter_kernel(const void* __restrict__ ei, int nE, int n) {
  int e = blockIdx.x * blockDim.x + threadIdx.x;
  if (e < nE) {
    int r = edge_val(ei, nE, e);
    int c = edge_val(ei, nE, nE + e);
    if ((unsigned)r < (unsigned)n && (unsigned)c < (unsigned)n) {
      int pos = atomicAdd(&g_cursor[c], 1);
      g_esrc[pos] = r;
      g_wn[pos] = g_dis[r] * g_dis[c];
    }
  }
}

// ---------------- SpMM: out[c] = sum_{edges into c} wn * h[src] ----------------
// warp per destination node; lane = feature chunk
template <int D>
__global__ void spmm_kernel(const float* __restrict__ hext, int hid, int outid, int n) {
  int w = (int)((blockIdx.x * blockDim.x + threadIdx.x) >> 5);
  int lane = threadIdx.x & 31;
  if (w >= n) return;
  const float* h = hext ? hext : bufp(hid);
  float* outp = bufp(outid);
  int j0 = g_rowptr[w], j1 = g_rowptr[w + 1];
  if (D == 128) {
    const float4* h4 = (const float4*)h;
    float4 acc = make_float4(0.f, 0.f, 0.f, 0.f);
    int j = j0;
    for (; j + 1 < j1; j += 2) {
      int s0 = g_esrc[j], s1 = g_esrc[j + 1];
      float w0 = g_wn[j], w1 = g_wn[j + 1];
      float4 v0 = h4[(size_t)s0 * 32 + lane];
      float4 v1 = h4[(size_t)s1 * 32 + lane];
      acc.x += w0 * v0.x + w1 * v1.x;
      acc.y += w0 * v0.y + w1 * v1.y;
      acc.z += w0 * v0.z + w1 * v1.z;
      acc.w += w0 * v0.w + w1 * v1.w;
    }
    if (j < j1) {
      int s0 = g_esrc[j];
      float w0 = g_wn[j];
      float4 v0 = h4[(size_t)s0 * 32 + lane];
      acc.x += w0 * v0.x; acc.y += w0 * v0.y;
      acc.z += w0 * v0.z; acc.w += w0 * v0.w;
    }
    ((float4*)outp)[(size_t)w * 32 + lane] = acc;
  } else {  // D == 64
    const float2* h2 = (const float2*)h;
    float2 acc = make_float2(0.f, 0.f);
    int j = j0;
    for (; j + 1 < j1; j += 2) {
      int s0 = g_esrc[j], s1 = g_esrc[j + 1];
      float w0 = g_wn[j], w1 = g_wn[j + 1];
      float2 v0 = h2[(size_t)s0 * 32 + lane];
      float2 v1 = h2[(size_t)s1 * 32 + lane];
      acc.x += w0 * v0.x + w1 * v1.x;
      acc.y += w0 * v0.y + w1 * v1.y;
    }
    if (j < j1) {
      int s0 = g_esrc[j];
      float w0 = g_wn[j];
      float2 v0 = h2[(size_t)s0 * 32 + lane];
      acc.x += w0 * v0.x; acc.y += w0 * v0.y;
    }
    ((float2*)outp)[(size_t)w * 32 + lane] = acc;
  }
}

// ---------------- dense: acc[m][o] += X[m][:] . W[o][:]  (W row-major [o][i]) ----------------
template <int DOUT, int DIN>
__global__ void gemm_acc_kernel(const float* __restrict__ Xext, int Xid,
                                const float* __restrict__ W,
                                float* __restrict__ accExt, int accId, int n) {
  constexpr int TM = 64, TK = 16;
  constexpr int CPT = DOUT / 16;  // cols per thread
  __shared__ float Xs[TM][TK + 1];
  __shared__ float Ws[DOUT][TK + 1];
  const float* X = Xext ? Xext : bufp(Xid);
  float* acc = accExt ? accExt : bufp(accId);
  int tid = threadIdx.x;   // 256 threads
  int cg = tid & 15;
  int rg = tid >> 4;       // 0..15
  int m0 = blockIdx.x * TM;
  float a[4][CPT];
#pragma unroll
  for (int i = 0; i < 4; i++)
#pragma unroll
    for (int j = 0; j < CPT; j++) a[i][j] = 0.f;

  for (int k0 = 0; k0 < DIN; k0 += TK) {
#pragma unroll
    for (int idx = tid; idx < DOUT * TK; idx += 256) {
      int o = idx / TK, kk = idx % TK;
      Ws[o][kk] = W[o * DIN + k0 + kk];
    }
#pragma unroll
    for (int idx = tid; idx < TM * TK; idx += 256) {
      int r = idx / TK, kk = idx % TK;
      int m = m0 + r;
      Xs[r][kk] = (m < n) ? X[(size_t)m * DIN + k0 + kk] : 0.f;
    }
    __syncthreads();
#pragma unroll
    for (int kk = 0; kk < TK; kk++) {
      float xv[4], wv[CPT];
#pragma unroll
      for (int i = 0; i < 4; i++) xv[i] = Xs[rg * 4 + i][kk];
#pragma unroll
      for (int j = 0; j < CPT; j++) wv[j] = Ws[cg + j * 16][kk];
#pragma unroll
      for (int i = 0; i < 4; i++)
#pragma unroll
        for (int j = 0; j < CPT; j++) a[i][j] += xv[i] * wv[j];
    }
    __syncthreads();
  }
#pragma unroll
  for (int i = 0; i < 4; i++) {
    int m = m0 + rg * 4 + i;
    if (m < n) {
#pragma unroll
      for (int j = 0; j < CPT; j++)
        acc[(size_t)m * DOUT + cg + j * 16] += a[i][j];
    }
  }
}

__global__ void init_bias_kernel(float* accExt, int accId, const float* __restrict__ b,
                                 int total, int doutMask) {
  int i = blockIdx.x * blockDim.x + threadIdx.x;
  float* acc = accExt ? accExt : bufp(accId);
  if (i < total) acc[i] = b[i & doutMask];
}

// ---------------- epilogues ----------------
__global__ void dropout_kernel(int tid_buf, int S, uint32_t k0, uint32_t k1) {
  int i = blockIdx.x * blockDim.x + threadIdx.x;
  if (i >= S) return;
  float* t = bufp(tid_buf);
  uint32_t o0, o1;
  threefry2x32(k0, k1, 0u, (uint32_t)i, o0, o1);
  uint32_t bits = o0 ^ o1;
  t[i] = (bits & 0x80000000u) ? 0.0f : 2.0f * t[i];
}

__global__ void elu_dropout_kernel(int tid_buf, int S, uint32_t k0, uint32_t k1) {
  int i = blockIdx.x * blockDim.x + threadIdx.x;
  if (i >= S) return;
  float* t = bufp(tid_buf);
  float v = t[i];
  v = (v > 0.f) ? v : expm1f(v);
  uint32_t o0, o1;
  threefry2x32(k0, k1, 0u, (uint32_t)i, o0, o1);
  uint32_t bits = o0 ^ o1;
  t[i] = (bits & 0x80000000u) ? 0.0f : 2.0f * v;
}

// ---------------- launch ----------------
// buffer ids: 0=g_h0, 1=g_h1, 2=g_t1, 3=g_t2
#define ID_H0 0
#define ID_H1 1
#define ID_T1 2
#define ID_T2 3

extern "C" void kernel_launch(void* const* d_in, const int* in_sizes, int n_in,
                              void* d_out, int out_size) {
  const float* x  = (const float*)d_in[0];
  const void*  ei = (const void*)d_in[1];
  const float* W1 = (const float*)d_in[2];
  const float* b1 = (const float*)d_in[3];
  const float* W2 = (const float*)d_in[4];
  const float* b2 = (const float*)d_in[5];
  const float* W3 = (const float*)d_in[6];
  const float* b3 = (const float*)d_in[7];
  float* out = (float*)d_out;

  const int n  = in_sizes[0] / 128;
  const int nE = in_sizes[1] / 2;   // (2, E) element count, dtype-independent

  // dropout keys: foldlike split of key(42)=(0,42) at 64-bit counters 0 and 1
  uint32_t d1k0, d1k1, d2k0, d2k1;
  threefry2x32(0u, 42u, 0u, 0u, d1k0, d1k1);
  threefry2x32(0u, 42u, 0u, 1u, d2k0, d2k1);

  const int TB = 256;
  int gN  = (n + TB - 1) / TB;
  int gE  = (nE + TB - 1) / TB;
  int gW  = (n * 32 + TB - 1) / TB;          // warp-per-node
  int gM  = (n + 63) / 64;                   // gemm row tiles

  // ---- graph preprocessing ----
  detect_kernel<<<1, 1>>>((const uint32_t*)ei);
  zero_hist_kernel<<<gN, TB>>>(n);
  hist_kernel<<<gE, TB>>>(ei, nE, n);
  dis_kernel<<<gN, TB>>>(n);
  scan_kernel<<<1, 1024>>>(n);
  scatter_kernel<<<gE, TB>>>(ei, nE, n);

  // ---- layer 1: din=128 dout=128, X = x, acc = t1 ----
  {
    int total = n * 128;
    init_bias_kernel<<<(total + TB - 1) / TB, TB>>>(nullptr, ID_T1, b1, total, 127);
    gemm_acc_kernel<128, 128><<<gM, TB>>>(x, -1, W1 + 0 * 128 * 128, nullptr, ID_T1, n);
    spmm_kernel<128><<<gW, TB>>>(x, -1, ID_H0, n);
    gemm_acc_kernel<128, 128><<<gM, TB>>>(nullptr, ID_H0, W1 + 1 * 128 * 128, nullptr, ID_T1, n);
    spmm_kernel<128><<<gW, TB>>>(nullptr, ID_H0, ID_H1, n);
    gemm_acc_kernel<128, 128><<<gM, TB>>>(nullptr, ID_H1, W1 + 2 * 128 * 128, nullptr, ID_T1, n);
    spmm_kernel<128><<<gW, TB>>>(nullptr, ID_H1, ID_H0, n);
    gemm_acc_kernel<128, 128><<<gM, TB>>>(nullptr, ID_H0, W1 + 3 * 128 * 128, nullptr, ID_T1, n);
    dropout_kernel<<<(total + TB - 1) / TB, TB>>>(ID_T1, total, d1k0, d1k1);
  }

  // ---- layer 2: din=128 dout=64, X = t1, acc = t2 ----
  {
    int total = n * 64;
    init_bias_kernel<<<(total + TB - 1) / TB, TB>>>(nullptr, ID_T2, b2, total, 63);
    gemm_acc_kernel<64, 128><<<gM, TB>>>(nullptr, ID_T1, W2 + 0 * 64 * 128, nullptr, ID_T2, n);
    spmm_kernel<128><<<gW, TB>>>(nullptr, ID_T1, ID_H0, n);
    gemm_acc_kernel<64, 128><<<gM, TB>>>(nullptr, ID_H0, W2 + 1 * 64 * 128, nullptr, ID_T2, n);
    spmm_kernel<128><<<gW, TB>>>(nullptr, ID_H0, ID_H1, n);
    gemm_acc_kernel<64, 128><<<gM, TB>>>(nullptr, ID_H1, W2 + 2 * 64 * 128, nullptr, ID_T2, n);
    spmm_kernel<128><<<gW, TB>>>(nullptr, ID_H1, ID_H0, n);
    gemm_acc_kernel<64, 128><<<gM, TB>>>(nullptr, ID_H0, W2 + 3 * 64 * 128, nullptr, ID_T2, n);
    elu_dropout_kernel<<<(total + TB - 1) / TB, TB>>>(ID_T2, total, d2k0, d2k1);
  }

  // ---- layer 3: din=64 dout=16, X = t2, acc = out ----
  {
    int total = n * 16;
    init_bias_kernel<<<(total + TB - 1) / TB, TB>>>(out, -1, b3, total, 15);
    gemm_acc_kernel<16, 64><<<gM, TB>>>(nullptr, ID_T2, W3 + 0 * 16 * 64, out, -1, n);
    spmm_kernel<64><<<gW, TB>>>(nullptr, ID_T2, ID_H0, n);
    gemm_acc_kernel<16, 64><<<gM, TB>>>(nullptr, ID_H0, W3 + 1 * 16 * 64, out, -1, n);
    spmm_kernel<64><<<gW, TB>>>(nullptr, ID_H0, ID_H1, n);
    gemm_acc_kernel<16, 64><<<gM, TB>>>(nullptr, ID_H1, W3 + 2 * 16 * 64, out, -1, n);
    spmm_kernel<64><<<gW, TB>>>(nullptr, ID_H1, ID_H0, n);
    gemm_acc_kernel<16, 64><<<gM, TB>>>(nullptr, ID_H0, W3 + 3 * 16 * 64, out, -1, n);
  }
}

// round 9
// speedup vs baseline: 1.2169x; 1.2169x over previous
#include <cuda_runtime.h>
#include <stdint.h>

#define N_MAX 100000
#define E_MAX 1600000

typedef unsigned long long ull;

// ---------------- scratch (device globals; no allocation) ----------------
__device__ float g_z[N_MAX * 512];     // Z = X @ Wcat^T (max 4*128 cols)
__device__ float g_h0[N_MAX * 128];
__device__ float g_h1[N_MAX * 128];
__device__ float g_t1[N_MAX * 128];    // layer1 output
__device__ float g_t2[N_MAX * 64];     // layer2 output
__device__ float g_dis[N_MAX];
__device__ float g_wn[E_MAX];
__device__ int   g_hist[N_MAX];
__device__ int   g_rowptr[N_MAX + 1];
__device__ int   g_cursor[N_MAX];
__device__ int   g_esrc[E_MAX];
__device__ int   g_is64;

// ids: 0=g_z 1=g_h0 2=g_h1 3=g_t1 4=g_t2
__device__ __forceinline__ float* bufp(int id) {
  switch (id) {
    case 0: return g_z;
    case 1: return g_h0;
    case 2: return g_h1;
    case 3: return g_t1;
    default: return g_t2;
  }
}

// ---------------- threefry2x32 (JAX-compatible) ----------------
__host__ __device__ static inline uint32_t rotl32(uint32_t v, int d) {
  return (v << d) | (v >> (32 - d));
}

__host__ __device__ static inline void threefry2x32(uint32_t k0, uint32_t k1,
                                                    uint32_t x0, uint32_t x1,
                                                    uint32_t& o0, uint32_t& o1) {
  uint32_t ks2 = k0 ^ k1 ^ 0x1BD11BDAu;
  x0 += k0; x1 += k1;
#define TF_R(r) { x0 += x1; x1 = rotl32(x1, (r)); x1 ^= x0; }
  TF_R(13) TF_R(15) TF_R(26) TF_R(6)
  x0 += k1; x1 += ks2 + 1u;
  TF_R(17) TF_R(29) TF_R(16) TF_R(24)
  x0 += ks2; x1 += k0 + 2u;
  TF_R(13) TF_R(15) TF_R(26) TF_R(6)
  x0 += k0; x1 += k1 + 3u;
  TF_R(17) TF_R(29) TF_R(16) TF_R(24)
  x0 += k1; x1 += ks2 + 4u;
  TF_R(13) TF_R(15) TF_R(26) TF_R(6)
  x0 += ks2; x1 += k0 + 5u;
#undef TF_R
  o0 = x0; o1 = x1;
}

// keep-mask: bit31 of o0^o1 of threefry(key, (0, i)) ; keep iff bit==0; scale x2
__device__ __forceinline__ float drop_apply(float v, uint32_t k0, uint32_t k1, uint32_t idx) {
  uint32_t o0, o1;
  threefry2x32(k0, k1, 0u, idx, o0, o1);
  return ((o0 ^ o1) & 0x80000000u) ? 0.0f : 2.0f * v;
}

// ---------------- edge dtype detection ----------------
__global__ void detect_kernel(const uint32_t* __restrict__ eiw) {
  int all0 = 1;
  for (int i = 0; i < 64; i++)
    if (eiw[2 * i + 1] != 0u) { all0 = 0; break; }
  g_is64 = all0;
}

__device__ __forceinline__ int edge_val(const void* ei, int nE, int idx) {
  if (g_is64) return (int)((const long long*)ei)[idx];
  return ((const int*)ei)[idx];
}

// ---------------- graph preprocessing ----------------
__global__ void zero_hist_kernel(int n) {
  int i = blockIdx.x * blockDim.x + threadIdx.x;
  if (i < n) g_hist[i] = 0;
}

__global__ void hist_kernel(const void* __restrict__ ei, int nE, int n) {
  int e = blockIdx.x * blockDim.x + threadIdx.x;
  if (e < nE) {
    int c = edge_val(ei, nE, nE + e);
    if ((unsigned)c < (unsigned)n) atomicAdd(&g_hist[c], 1);
  }
}

__global__ void dis_kernel(int n) {
  int i = blockIdx.x * blockDim.x + threadIdx.x;
  if (i < n) {
    int d = g_hist[i];
    g_dis[i] = (d > 0) ? rsqrtf((float)d) : 0.0f;
  }
}

__global__ void scan_kernel(int n) {
  __shared__ int buf[1024];
  __shared__ int carry_s;
  int tid = threadIdx.x;
  if (tid == 0) carry_s = 0;
  __syncthreads();
  for (int base = 0; base < n; base += 1024) {
    int v = (base + tid < n) ? g_hist[base + tid] : 0;
    buf[tid] = v;
    __syncthreads();
    for (int off = 1; off < 1024; off <<= 1) {
      int t = (tid >= off) ? buf[tid - off] : 0;
      __syncthreads();
      buf[tid] += t;
      __syncthreads();
    }
    int carry = carry_s;
    int excl = carry + buf[tid] - v;
    if (base + tid < n) { g_rowptr[base + tid] = excl; g_cursor[base + tid] = excl; }
    __syncthreads();
    if (tid == 0) carry_s = carry + buf[1023];
    __syncthreads();
  }
  if (tid == 0) g_rowptr[n] = carry_s;
}

__global__ void scatter_kernel(const void* __restrict__ ei, int nE, int n) {
  int e = blockIdx.x * blockDim.x + threadIdx.x;
  if (e < nE) {
    int r = edge_val(ei, nE, e);
    int c = edge_val(ei, nE, nE + e);
    if ((unsigned)r < (unsigned)n && (unsigned)c < (unsigned)n) {
      int pos = atomicAdd(&g_cursor[c], 1);
      g_esrc[pos] = r;
      g_wn[pos] = g_dis[r] * g_dis[c];
    }
  }
}

// ---------------- GEMM: g_z[m][o] = sum_i X[m][i] * W[o][i] ----------------
// TM=128, TN=64, TK=16, 256 threads, 8x4 microtile via packed f32x2 FMA.
#define FFMA2(acc, a, b) asm("fma.rn.f32x2 %0, %1, %2, %0;" : "+l"(acc) : "l"(a), "l"(b))

union F4U2 { float4 f4; ull u2[2]; float f[4]; };

template <int DIN, int NOUT>
__global__ __launch_bounds__(256) void gemm_kernel(const float* __restrict__ Xext, int Xid,
                                                   const float* __restrict__ W, int n) {
  constexpr int TM = 128, TN = 64, TK = 16;
  constexpr int XS = TM + 4;      // 132 floats: 16B-aligned row stride
  constexpr int WS = 2 * TN + 4;  // 132
  __shared__ float XsT[TK][XS];   // [kk][row]
  __shared__ float WsT[TK][WS];   // [kk][2*col] duplicated pairs (w,w)
  const float* X = Xext ? Xext : bufp(Xid);
  int t = threadIdx.x;
  int m0 = blockIdx.x * TM;
  int n0 = blockIdx.y * TN;
  int ty = t >> 4, tx = t & 15;
  int lrow = t >> 1;            // 0..127
  int lkb  = (t & 1) * 8;       // 0 / 8
  int wcol = t >> 2;            // 0..63
  int wkb  = (t & 3) * 4;       // 0,4,8,12

  ull acc[4][4];
#pragma unroll
  for (int i = 0; i < 4; i++)
#pragma unroll
    for (int j = 0; j < 4; j++) acc[i][j] = 0ull;

  for (int k0 = 0; k0 < DIN; k0 += TK) {
    float4 xa, xb;
    int m = m0 + lrow;
    if (m < n) {
      const float4* xp = (const float4*)(X + (size_t)m * DIN + k0 + lkb);
      xa = xp[0]; xb = xp[1];
    } else {
      xa = make_float4(0.f, 0.f, 0.f, 0.f); xb = xa;
    }
    const float4* wp = (const float4*)(W + (size_t)(n0 + wcol) * DIN + k0 + wkb);
    float4 wv = *wp;

    __syncthreads();
    XsT[lkb + 0][lrow] = xa.x; XsT[lkb + 1][lrow] = xa.y;
    XsT[lkb + 2][lrow] = xa.z; XsT[lkb + 3][lrow] = xa.w;
    XsT[lkb + 4][lrow] = xb.x; XsT[lkb + 5][lrow] = xb.y;
    XsT[lkb + 6][lrow] = xb.z; XsT[lkb + 7][lrow] = xb.w;
    WsT[wkb + 0][wcol * 2] = wv.x; WsT[wkb + 0][wcol * 2 + 1] = wv.x;
    WsT[wkb + 1][wcol * 2] = wv.y; WsT[wkb + 1][wcol * 2 + 1] = wv.y;
    WsT[wkb + 2][wcol * 2] = wv.z; WsT[wkb + 2][wcol * 2 + 1] = wv.z;
    WsT[wkb + 3][wcol * 2] = wv.w; WsT[wkb + 3][wcol * 2 + 1] = wv.w;
    __syncthreads();

#pragma unroll
    for (int kk = 0; kk < TK; kk++) {
      F4U2 x0, x1, w0, w1;
      x0.f4 = *(const float4*)&XsT[kk][ty * 8];
      x1.f4 = *(const float4*)&XsT[kk][ty * 8 + 4];
      w0.f4 = *(const float4*)&WsT[kk][tx * 8];
      w1.f4 = *(const float4*)&WsT[kk][tx * 8 + 4];
      ull xr[4] = {x0.u2[0], x0.u2[1], x1.u2[0], x1.u2[1]};
      ull wr[4] = {w0.u2[0], w0.u2[1], w1.u2[0], w1.u2[1]};
#pragma unroll
      for (int i = 0; i < 4; i++)
#pragma unroll
        for (int j = 0; j < 4; j++) FFMA2(acc[i][j], xr[i], wr[j]);
    }
  }

#pragma unroll
  for (int i = 0; i < 8; i++) {
    int r = m0 + ty * 8 + i;
    if (r < n) {
      int i2 = i >> 1, hi = i & 1;
      float4 v;
      v.x = ((const float2*)&acc[i2][0])->x * 0.f + (hi ? ((const float2*)&acc[i2][0])->y : ((const float2*)&acc[i2][0])->x);
      v.y = hi ? ((const float2*)&acc[i2][1])->y : ((const float2*)&acc[i2][1])->x;
      v.z = hi ? ((const float2*)&acc[i2][2])->y : ((const float2*)&acc[i2][2])->x;
      v.w = hi ? ((const float2*)&acc[i2][3])->y : ((const float2*)&acc[i2][3])->x;
      *(float4*)(g_z + (size_t)r * NOUT + n0 + tx * 4) = v;
    }
  }
}

// ---------------- SpMM (Horner step): out = A*h + z (+bias, +elu, +dropout) ----------------
// EPI: 0 = none; 1 = bias+dropout; 2 = bias+elu+dropout; 3 = bias only
template <int D, int EPI>
__global__ void spmm_kernel(const float* __restrict__ hExt, int hId, int hOff, int hStride,
                            int zOff, int zStride,
                            float* __restrict__ outExt, int outId,
                            const float* __restrict__ bias, int n,
                            uint32_t k0, uint32_t k1) {
  int gt = blockIdx.x * blockDim.x + threadIdx.x;
  int lane = threadIdx.x & 31;
  const float* h = (hExt ? hExt : bufp(hId)) + hOff;
  float* outp = outExt ? outExt : bufp(outId);

  if (D == 128) {
    int node = gt >> 5;
    if (node >= n) return;
    int j0 = g_rowptr[node], j1 = g_rowptr[node + 1];
    const float4* h4 = (const float4*)h;
    int hs4 = hStride >> 2;
    size_t zbase = (size_t)node * zStride + zOff;
    float4 a = *(const float4*)(g_z + zbase + lane * 4);
    float4 b = make_float4(0.f, 0.f, 0.f, 0.f);
    int j = j0;
    for (; j + 3 < j1; j += 4) {
      int s0 = g_esrc[j], s1 = g_esrc[j + 1], s2 = g_esrc[j + 2], s3 = g_esrc[j + 3];
      float w0 = g_wn[j], w1 = g_wn[j + 1], w2 = g_wn[j + 2], w3 = g_wn[j + 3];
      float4 v0 = h4[(size_t)s0 * hs4 + lane];
      float4 v1 = h4[(size_t)s1 * hs4 + lane];
      float4 v2 = h4[(size_t)s2 * hs4 + lane];
      float4 v3 = h4[(size_t)s3 * hs4 + lane];
      a.x += w0 * v0.x; a.y += w0 * v0.y; a.z += w0 * v0.z; a.w += w0 * v0.w;
      b.x += w1 * v1.x; b.y += w1 * v1.y; b.z += w1 * v1.z; b.w += w1 * v1.w;
      a.x += w2 * v2.x; a.y += w2 * v2.y; a.z += w2 * v2.z; a.w += w2 * v2.w;
      b.x += w3 * v3.x; b.y += w3 * v3.y; b.z += w3 * v3.z; b.w += w3 * v3.w;
    }
    for (; j < j1; j++) {
      int s = g_esrc[j]; float w = g_wn[j];
      float4 v = h4[(size_t)s * hs4 + lane];
      a.x += w * v.x; a.y += w * v.y; a.z += w * v.z; a.w += w * v.w;
    }
    a.x += b.x; a.y += b.y; a.z += b.z; a.w += b.w;
    if (EPI >= 1) {
      float4 bb = ((const float4*)bias)[lane];
      a.x += bb.x; a.y += bb.y; a.z += bb.z; a.w += bb.w;
      if (EPI == 2) {
        a.x = (a.x > 0.f) ? a.x : expm1f(a.x);
        a.y = (a.y > 0.f) ? a.y : expm1f(a.y);
        a.z = (a.z > 0.f) ? a.z : expm1f(a.z);
        a.w = (a.w > 0.f) ? a.w : expm1f(a.w);
      }
      if (EPI <= 2) {
        uint32_t ib = (uint32_t)node * 128u + lane * 4u;
        a.x = drop_apply(a.x, k0, k1, ib + 0u);
        a.y = drop_apply(a.y, k0, k1, ib + 1u);
        a.z = drop_apply(a.z, k0, k1, ib + 2u);
        a.w = drop_apply(a.w, k0, k1, ib + 3u);
      }
    }
    ((float4*)outp)[(size_t)node * 32 + lane] = a;
  } else if (D == 64) {
    int node = gt >> 5;
    if (node >= n) return;
    int j0 = g_rowptr[node], j1 = g_rowptr[node + 1];
    const float2* h2 = (const float2*)h;
    int hs2 = hStride >> 1;
    size_t zbase = (size_t)node * zStride + zOff;
    float2 a = *(const float2*)(g_z + zbase + lane * 2);
    float2 b = make_float2(0.f, 0.f);
    int j = j0;
    for (; j + 3 < j1; j += 4) {
      int s0 = g_esrc[j], s1 = g_esrc[j + 1], s2 = g_esrc[j + 2], s3 = g_esrc[j + 3];
      float w0 = g_wn[j], w1 = g_wn[j + 1], w2 = g_wn[j + 2], w3 = g_wn[j + 3];
      float2 v0 = h2[(size_t)s0 * hs2 + lane];
      float2 v1 = h2[(size_t)s1 * hs2 + lane];
      float2 v2 = h2[(size_t)s2 * hs2 + lane];
      float2 v3 = h2[(size_t)s3 * hs2 + lane];
      a.x += w0 * v0.x; a.y += w0 * v0.y;
      b.x += w1 * v1.x; b.y += w1 * v1.y;
      a.x += w2 * v2.x; a.y += w2 * v2.y;
      b.x += w3 * v3.x; b.y += w3 * v3.y;
    }
    for (; j < j1; j++) {
      int s = g_esrc[j]; float w = g_wn[j];
      float2 v = h2[(size_t)s * hs2 + lane];
      a.x += w * v.x; a.y += w * v.y;
    }
    a.x += b.x; a.y += b.y;
    if (EPI >= 1) {
      float2 bb = ((const float2*)bias)[lane];
      a.x += bb.x; a.y += bb.y;
      if (EPI == 2) {
        a.x = (a.x > 0.f) ? a.x : expm1f(a.x);
        a.y = (a.y > 0.f) ? a.y : expm1f(a.y);
      }
      if (EPI <= 2) {
        uint32_t ib = (uint32_t)node * 64u + lane * 2u;
        a.x = drop_apply(a.x, k0, k1, ib + 0u);
        a.y = drop_apply(a.y, k0, k1, ib + 1u);
      }
    }
    ((float2*)outp)[(size_t)node * 32 + lane] = a;
  } else {  // D == 16: two nodes per warp, 16 lanes each
    int node = (gt >> 5) * 2 + (lane >> 4);
    int l16 = lane & 15;
    if (node >= n) return;
    int j0 = g_rowptr[node], j1 = g_rowptr[node + 1];
    float a = g_z[(size_t)node * zStride + zOff + l16];
    float b = 0.f;
    int j = j0;
    for (; j + 1 < j1; j += 2) {
      int s0 = g_esrc[j], s1 = g_esrc[j + 1];
      a += g_wn[j] * h[(size_t)s0 * hStride + l16];
      b += g_wn[j + 1] * h[(size_t)s1 * hStride + l16];
    }
    if (j < j1) a += g_wn[j] * h[(size_t)g_esrc[j] * hStride + l16];
    a += b;
    if (EPI >= 1) a += bias[l16];
    outp[(size_t)node * 16 + l16] = a;
  }
}

// ---------------- launch ----------------
#define ID_Z  0
#define ID_H0 1
#define ID_H1 2
#define ID_T1 3
#define ID_T2 4

extern "C" void kernel_launch(void* const* d_in, const int* in_sizes, int n_in,
                              void* d_out, int out_size) {
  const float* x  = (const float*)d_in[0];
  const void*  ei = (const void*)d_in[1];
  const float* W1 = (const float*)d_in[2];
  const float* b1 = (const float*)d_in[3];
  const float* W2 = (const float*)d_in[4];
  const float* b2 = (const float*)d_in[5];
  const float* W3 = (const float*)d_in[6];
  const float* b3 = (const float*)d_in[7];
  float* out = (float*)d_out;

  const int n  = in_sizes[0] / 128;
  const int nE = in_sizes[1] / 2;

  uint32_t d1k0, d1k1, d2k0, d2k1;
  threefry2x32(0u, 42u, 0u, 0u, d1k0, d1k1);
  threefry2x32(0u, 42u, 0u, 1u, d2k0, d2k1);

  const int TB = 256;
  int gN   = (n + TB - 1) / TB;
  int gE   = (nE + TB - 1) / TB;
  int gW   = ((long long)n * 32 + TB - 1) / TB;        // warp per node
  int gW16 = (((n + 1) / 2) * 32 + TB - 1) / TB;       // 2 nodes per warp
  int mT   = (n + 127) / 128;

  // ---- graph preprocessing ----
  detect_kernel<<<1, 1>>>((const uint32_t*)ei);
  zero_hist_kernel<<<gN, TB>>>(n);
  hist_kernel<<<gE, TB>>>(ei, nE, n);
  dis_kernel<<<gN, TB>>>(n);
  scan_kernel<<<1, 1024>>>(n);
  scatter_kernel<<<gE, TB>>>(ei, nE, n);

  // ---- layer 1: din=128 dout=128 (Z: 512 cols) ----
  gemm_kernel<128, 512><<<dim3(mT, 8), 256>>>(x, -1, W1, n);
  spmm_kernel<128, 0><<<gW, TB>>>(nullptr, ID_Z, 3 * 128, 512, 2 * 128, 512,
                                  nullptr, ID_H0, nullptr, n, 0u, 0u);
  spmm_kernel<128, 0><<<gW, TB>>>(nullptr, ID_H0, 0, 128, 1 * 128, 512,
                                  nullptr, ID_H1, nullptr, n, 0u, 0u);
  spmm_kernel<128, 1><<<gW, TB>>>(nullptr, ID_H1, 0, 128, 0, 512,
                                  nullptr, ID_T1, b1, n, d1k0, d1k1);

  // ---- layer 2: din=128 dout=64 (Z: 256 cols) ----
  gemm_kernel<128, 256><<<dim3(mT, 4), 256>>>(nullptr, ID_T1, W2, n);
  spmm_kernel<64, 0><<<gW, TB>>>(nullptr, ID_Z, 3 * 64, 256, 2 * 64, 256,
                                 nullptr, ID_H0, nullptr, n, 0u, 0u);
  spmm_kernel<64, 0><<<gW, TB>>>(nullptr, ID_H0, 0, 64, 1 * 64, 256,
                                 nullptr, ID_H1, nullptr, n, 0u, 0u);
  spmm_kernel<64, 2><<<gW, TB>>>(nullptr, ID_H1, 0, 64, 0, 256,
                                 nullptr, ID_T2, b2, n, d2k0, d2k1);

  // ---- layer 3: din=64 dout=16 (Z: 64 cols) ----
  gemm_kernel<64, 64><<<dim3(mT, 1), 256>>>(nullptr, ID_T2, W3, n);
  spmm_kernel<16, 0><<<gW16, TB>>>(nullptr, ID_Z, 3 * 16, 64, 2 * 16, 64,
                                   nullptr, ID_H0, nullptr, n, 0u, 0u);
  spmm_kernel<16, 0><<<gW16, TB>>>(nullptr, ID_H0, 0, 16, 1 * 16, 64,
                                   nullptr, ID_H1, nullptr, n, 0u, 0u);
  spmm_kernel<16, 3><<<gW16, TB>>>(nullptr, ID_H1, 0, 16, 0, 64,
                                   out, -1, b3, n, 0u, 0u);
}

// round 10
// speedup vs baseline: 1.3331x; 1.0955x over previous
#include <cuda_runtime.h>
#include <stdint.h>

#define N_MAX 100000
#define E_MAX 1600000

typedef unsigned long long ull;

// ---------------- scratch (device globals; no allocation) ----------------
__device__ float g_z[N_MAX * 512];     // 4 compact hop buffers: z_k at k*n*DOUT
__device__ float g_h0[N_MAX * 128];
__device__ float g_h1[N_MAX * 128];
__device__ float g_t1[N_MAX * 128];
__device__ float g_t2[N_MAX * 64];
__device__ float g_dis[N_MAX];
__device__ float g_wn[E_MAX];
__device__ int   g_hist[N_MAX];
__device__ int   g_rowptr[N_MAX + 1];
__device__ int   g_cursor[N_MAX];
__device__ int   g_esrc[E_MAX];
__device__ int   g_is64;
__device__ int   g_bsum[256];
__device__ int   g_boff[256];
__device__ int   g_total;

// ids: 0=g_z 1=g_h0 2=g_h1 3=g_t1 4=g_t2
__device__ __forceinline__ float* bufp(int id) {
  switch (id) {
    case 0: return g_z;
    case 1: return g_h0;
    case 2: return g_h1;
    case 3: return g_t1;
    default: return g_t2;
  }
}

// ---------------- threefry2x32 (JAX-compatible) ----------------
__host__ __device__ static inline uint32_t rotl32(uint32_t v, int d) {
  return (v << d) | (v >> (32 - d));
}

__host__ __device__ static inline void threefry2x32(uint32_t k0, uint32_t k1,
                                                    uint32_t x0, uint32_t x1,
                                                    uint32_t& o0, uint32_t& o1) {
  uint32_t ks2 = k0 ^ k1 ^ 0x1BD11BDAu;
  x0 += k0; x1 += k1;
#define TF_R(r) { x0 += x1; x1 = rotl32(x1, (r)); x1 ^= x0; }
  TF_R(13) TF_R(15) TF_R(26) TF_R(6)
  x0 += k1; x1 += ks2 + 1u;
  TF_R(17) TF_R(29) TF_R(16) TF_R(24)
  x0 += ks2; x1 += k0 + 2u;
  TF_R(13) TF_R(15) TF_R(26) TF_R(6)
  x0 += k0; x1 += k1 + 3u;
  TF_R(17) TF_R(29) TF_R(16) TF_R(24)
  x0 += k1; x1 += ks2 + 4u;
  TF_R(13) TF_R(15) TF_R(26) TF_R(6)
  x0 += ks2; x1 += k0 + 5u;
#undef TF_R
  o0 = x0; o1 = x1;
}

__device__ __forceinline__ float drop_apply(float v, uint32_t k0, uint32_t k1, uint32_t idx) {
  uint32_t o0, o1;
  threefry2x32(k0, k1, 0u, idx, o0, o1);
  return ((o0 ^ o1) & 0x80000000u) ? 0.0f : 2.0f * v;
}

// ---------------- preprocessing kernels ----------------
// idx0: zero hist + edge dtype detection (block 0 thread 0)
__global__ void zero_detect_kernel(const uint32_t* __restrict__ eiw, int n) {
  int i = blockIdx.x * blockDim.x + threadIdx.x;
  if (i < n) g_hist[i] = 0;
  if (blockIdx.x == 0 && threadIdx.x == 0) {
    int all0 = 1;
    for (int k = 0; k < 64; k++)
      if (eiw[2 * k + 1] != 0u) { all0 = 0; break; }
    g_is64 = all0;
  }
}

__device__ __forceinline__ int edge_val(const void* ei, int nE, int idx) {
  if (g_is64) return (int)((const long long*)ei)[idx];
  return ((const int*)ei)[idx];
}

// idx1: in-degree histogram
__global__ void hist_kernel(const void* __restrict__ ei, int nE, int n) {
  int e = blockIdx.x * blockDim.x + threadIdx.x;
  if (e < nE) {
    int c = edge_val(ei, nE, nE + e);
    if ((unsigned)c < (unsigned)n) atomicAdd(&g_hist[c], 1);
  }
}

// idx2: per-block inclusive scan of hist -> g_cursor (temp), block sums, dis
__global__ void scan_partial_dis_kernel(int n) {
  __shared__ int wsum[32];
  int tid = threadIdx.x;
  int i = blockIdx.x * 1024 + tid;
  int v = (i < n) ? g_hist[i] : 0;
  if (i < n) g_dis[i] = (v > 0) ? rsqrtf((float)v) : 0.0f;
  int lane = tid & 31, wid = tid >> 5;
  int s = v;
#pragma unroll
  for (int off = 1; off < 32; off <<= 1) {
    int t = __shfl_up_sync(0xFFFFFFFFu, s, off);
    if (lane >= off) s += t;
  }
  if (lane == 31) wsum[wid] = s;
  __syncthreads();
  if (wid == 0) {
    int w = (lane < 32) ? wsum[lane] : 0;
#pragma unroll
    for (int off = 1; off < 32; off <<= 1) {
      int t = __shfl_up_sync(0xFFFFFFFFu, w, off);
      if (lane >= off) w += t;
    }
    wsum[lane] = w;
  }
  __syncthreads();
  int incl = s + (wid > 0 ? wsum[wid - 1] : 0);
  if (i < n) g_cursor[i] = incl;   // inclusive within block (temp)
  if (tid == 1023) g_bsum[blockIdx.x] = incl;
}

// idx4: single-block exclusive scan of block sums
__global__ void scan_totals_kernel(int nb) {
  __shared__ int buf[256];
  int tid = threadIdx.x;  // 256
  int v = (tid < nb) ? g_bsum[tid] : 0;
  buf[tid] = v;
  __syncthreads();
#pragma unroll
  for (int off = 1; off < 256; off <<= 1) {
    int t = (tid >= off) ? buf[tid - off] : 0;
    __syncthreads();
    buf[tid] += t;
    __syncthreads();
  }
  if (tid < nb) g_boff[tid] = buf[tid] - v;  // exclusive
  if (tid == 255) g_total = buf[255];
}

// idx5: finalize rowptr/cursor
__global__ void scan_add_kernel(int n) {
  int i = blockIdx.x * blockDim.x + threadIdx.x;
  if (i < n) {
    int excl = g_cursor[i] - g_hist[i] + g_boff[i >> 10];
    g_rowptr[i] = excl;
    g_cursor[i] = excl;
  }
  if (i == 0) g_rowptr[n] = g_total;
}

// idx6: CSR scatter + edge weights
__global__ void scatter_kernel(const void* __restrict__ ei, int nE, int n) {
  int e = blockIdx.x * blockDim.x + threadIdx.x;
  if (e < nE) {
    int r = edge_val(ei, nE, e);
    int c = edge_val(ei, nE, nE + e);
    if ((unsigned)r < (unsigned)n && (unsigned)c < (unsigned)n) {
      int pos = atomicAdd(&g_cursor[c], 1);
      g_esrc[pos] = r;
      g_wn[pos] = g_dis[r] * g_dis[c];
    }
  }
}

// ---------------- GEMM: z_k[m][o] = sum_i X[m][i] * W[k*DOUT+o][i] ----------------
// TM=128, TN=64, TK=16, 256 threads, 8x4 microtile, packed f32x2 FMA,
// register-prefetch software pipeline. Writes to compact z_k buffers.
#define FFMA2(acc, a, b) asm("fma.rn.f32x2 %0, %1, %2, %0;" : "+l"(acc) : "l"(a), "l"(b))

union F4U2 { float4 f4; ull u2[2]; float f[4]; };

template <int DIN, int DOUT>
__global__ __launch_bounds__(256) void gemm_kernel(const float* __restrict__ Xext, int Xid,
                                                   const float* __restrict__ W, int n) {
  constexpr int TM = 128, TN = 64, TK = 16;
  constexpr int XS = TM + 4;
  constexpr int WS = 2 * TN + 4;
  __shared__ float XsT[TK][XS];   // [kk][row]
  __shared__ float WsT[TK][WS];   // [kk][2*col] duplicated (w,w)
  const float* X = Xext ? Xext : bufp(Xid);
  int t = threadIdx.x;
  int m0 = blockIdx.x * TM;
  int n0 = blockIdx.y * TN;     // global output column base (0..4*DOUT)
  int ty = t >> 4, tx = t & 15;
  int lrow = t >> 1;
  int lkb  = (t & 1) * 8;
  int wcol = t >> 2;
  int wkb  = (t & 3) * 4;
  int mrow = m0 + lrow;

  ull acc[4][4];
#pragma unroll
  for (int i = 0; i < 4; i++)
#pragma unroll
    for (int j = 0; j < 4; j++) acc[i][j] = 0ull;

  // prologue prefetch (k0 = 0)
  float4 xa, xb, wv;
  if (mrow < n) {
    const float4* xp = (const float4*)(X + (size_t)mrow * DIN + lkb);
    xa = xp[0]; xb = xp[1];
  } else {
    xa = make_float4(0.f, 0.f, 0.f, 0.f); xb = xa;
  }
  wv = *(const float4*)(W + (size_t)(n0 + wcol) * DIN + wkb);

  for (int k0 = 0; k0 < DIN; k0 += TK) {
    __syncthreads();
    XsT[lkb + 0][lrow] = xa.x; XsT[lkb + 1][lrow] = xa.y;
    XsT[lkb + 2][lrow] = xa.z; XsT[lkb + 3][lrow] = xa.w;
    XsT[lkb + 4][lrow] = xb.x; XsT[lkb + 5][lrow] = xb.y;
    XsT[lkb + 6][lrow] = xb.z; XsT[lkb + 7][lrow] = xb.w;
    WsT[wkb + 0][wcol * 2] = wv.x; WsT[wkb + 0][wcol * 2 + 1] = wv.x;
    WsT[wkb + 1][wcol * 2] = wv.y; WsT[wkb + 1][wcol * 2 + 1] = wv.y;
    WsT[wkb + 2][wcol * 2] = wv.z; WsT[wkb + 2][wcol * 2 + 1] = wv.z;
    WsT[wkb + 3][wcol * 2] = wv.w; WsT[wkb + 3][wcol * 2 + 1] = wv.w;
    __syncthreads();

    // prefetch next tile (LDG in flight while we compute this tile)
    int kn = k0 + TK;
    if (kn < DIN) {
      if (mrow < n) {
        const float4* xp = (const float4*)(X + (size_t)mrow * DIN + kn + lkb);
        xa = xp[0]; xb = xp[1];
      } else {
        xa = make_float4(0.f, 0.f, 0.f, 0.f); xb = xa;
      }
      wv = *(const float4*)(W + (size_t)(n0 + wcol) * DIN + kn + wkb);
    }

#pragma unroll
    for (int kk = 0; kk < TK; kk++) {
      F4U2 x0, x1, w0, w1;
      x0.f4 = *(const float4*)&XsT[kk][ty * 8];
      x1.f4 = *(const float4*)&XsT[kk][ty * 8 + 4];
      w0.f4 = *(const float4*)&WsT[kk][tx * 8];
      w1.f4 = *(const float4*)&WsT[kk][tx * 8 + 4];
      ull xr[4] = {x0.u2[0], x0.u2[1], x1.u2[0], x1.u2[1]};
      ull wr[4] = {w0.u2[0], w0.u2[1], w1.u2[0], w1.u2[1]};
#pragma unroll
      for (int i = 0; i < 4; i++)
#pragma unroll
        for (int j = 0; j < 4; j++) FFMA2(acc[i][j], xr[i], wr[j]);
    }
  }

  // epilogue: write to compact z_k buffer (k = col/DOUT)
  int col = n0 + tx * 4;
  int hop = col / DOUT;
  int cib = col - hop * DOUT;
  float* zb = g_z + (size_t)hop * n * DOUT;
#pragma unroll
  for (int i = 0; i < 8; i++) {
    int r = m0 + ty * 8 + i;
    if (r < n) {
      int i2 = i >> 1, hi = i & 1;
      float4 v;
      float2 p0 = *(const float2*)&acc[i2][0];
      float2 p1 = *(const float2*)&acc[i2][1];
      float2 p2 = *(const float2*)&acc[i2][2];
      float2 p3 = *(const float2*)&acc[i2][3];
      v.x = hi ? p0.y : p0.x;
      v.y = hi ? p1.y : p1.x;
      v.z = hi ? p2.y : p2.x;
      v.w = hi ? p3.y : p3.x;
      *(float4*)(zb + (size_t)r * DOUT + cib) = v;
    }
  }
}

// ---------------- SpMM (Horner step): out = A*h + z (+bias,+elu,+dropout) ----------------
// all buffers compact stride-D. EPI: 0 none; 1 bias+dropout; 2 bias+elu+dropout; 3 bias only
template <int D, int EPI>
__global__ void spmm_kernel(int hId, size_t hOff, size_t zOff,
                            float* __restrict__ outExt, int outId,
                            const float* __restrict__ bias, int n,
                            uint32_t k0, uint32_t k1) {
  int gt = blockIdx.x * blockDim.x + threadIdx.x;
  int lane = threadIdx.x & 31;
  const float* h = bufp(hId) + hOff;
  const float* z = g_z + zOff;
  float* outp = outExt ? outExt : bufp(outId);

  if (D == 128) {
    int node = gt >> 5;
    if (node >= n) return;
    int j0 = g_rowptr[node], j1 = g_rowptr[node + 1];
    const float4* h4 = (const float4*)h;
    float4 a = *(const float4*)(z + (size_t)node * 128 + lane * 4);
    float4 b = make_float4(0.f, 0.f, 0.f, 0.f);
    int j = j0;
    for (; j + 3 < j1; j += 4) {
      int s0 = g_esrc[j], s1 = g_esrc[j + 1], s2 = g_esrc[j + 2], s3 = g_esrc[j + 3];
      float w0 = g_wn[j], w1 = g_wn[j + 1], w2 = g_wn[j + 2], w3 = g_wn[j + 3];
      float4 v0 = h4[(size_t)s0 * 32 + lane];
      float4 v1 = h4[(size_t)s1 * 32 + lane];
      float4 v2 = h4[(size_t)s2 * 32 + lane];
      float4 v3 = h4[(size_t)s3 * 32 + lane];
      a.x += w0 * v0.x; a.y += w0 * v0.y; a.z += w0 * v0.z; a.w += w0 * v0.w;
      b.x += w1 * v1.x; b.y += w1 * v1.y; b.z += w1 * v1.z; b.w += w1 * v1.w;
      a.x += w2 * v2.x; a.y += w2 * v2.y; a.z += w2 * v2.z; a.w += w2 * v2.w;
      b.x += w3 * v3.x; b.y += w3 * v3.y; b.z += w3 * v3.z; b.w += w3 * v3.w;
    }
    for (; j < j1; j++) {
      int s = g_esrc[j]; float w = g_wn[j];
      float4 v = h4[(size_t)s * 32 + lane];
      a.x += w * v.x; a.y += w * v.y; a.z += w * v.z; a.w += w * v.w;
    }
    a.x += b.x; a.y += b.y; a.z += b.z; a.w += b.w;
    if (EPI >= 1) {
      float4 bb = ((const float4*)bias)[lane];
      a.x += bb.x; a.y += bb.y; a.z += bb.z; a.w += bb.w;
      if (EPI == 2) {
        a.x = (a.x > 0.f) ? a.x : expm1f(a.x);
        a.y = (a.y > 0.f) ? a.y : expm1f(a.y);
        a.z = (a.z > 0.f) ? a.z : expm1f(a.z);
        a.w = (a.w > 0.f) ? a.w : expm1f(a.w);
      }
      if (EPI <= 2) {
        uint32_t ib = (uint32_t)node * 128u + lane * 4u;
        a.x = drop_apply(a.x, k0, k1, ib + 0u);
        a.y = drop_apply(a.y, k0, k1, ib + 1u);
        a.z = drop_apply(a.z, k0, k1, ib + 2u);
        a.w = drop_apply(a.w, k0, k1, ib + 3u);
      }
    }
    ((float4*)outp)[(size_t)node * 32 + lane] = a;
  } else if (D == 64) {
    int node = gt >> 5;
    if (node >= n) return;
    int j0 = g_rowptr[node], j1 = g_rowptr[node + 1];
    const float2* h2 = (const float2*)h;
    float2 a = *(const float2*)(z + (size_t)node * 64 + lane * 2);
    float2 b = make_float2(0.f, 0.f);
    int j = j0;
    for (; j + 3 < j1; j += 4) {
      int s0 = g_esrc[j], s1 = g_esrc[j + 1], s2 = g_esrc[j + 2], s3 = g_esrc[j + 3];
      float w0 = g_wn[j], w1 = g_wn[j + 1], w2 = g_wn[j + 2], w3 = g_wn[j + 3];
      float2 v0 = h2[(size_t)s0 * 32 + lane];
      float2 v1 = h2[(size_t)s1 * 32 + lane];
      float2 v2 = h2[(size_t)s2 * 32 + lane];
      float2 v3 = h2[(size_t)s3 * 32 + lane];
      a.x += w0 * v0.x; a.y += w0 * v0.y;
      b.x += w1 * v1.x; b.y += w1 * v1.y;
      a.x += w2 * v2.x; a.y += w2 * v2.y;
      b.x += w3 * v3.x; b.y += w3 * v3.y;
    }
    for (; j < j1; j++) {
      int s = g_esrc[j]; float w = g_wn[j];
      float2 v = h2[(size_t)s * 32 + lane];
      a.x += w * v.x; a.y += w * v.y;
    }
    a.x += b.x; a.y += b.y;
    if (EPI >= 1) {
      float2 bb = ((const float2*)bias)[lane];
      a.x += bb.x; a.y += bb.y;
      if (EPI == 2) {
        a.x = (a.x > 0.f) ? a.x : expm1f(a.x);
        a.y = (a.y > 0.f) ? a.y : expm1f(a.y);
      }
      if (EPI <= 2) {
        uint32_t ib = (uint32_t)node * 64u + lane * 2u;
        a.x = drop_apply(a.x, k0, k1, ib + 0u);
        a.y = drop_apply(a.y, k0, k1, ib + 1u);
      }
    }
    ((float2*)outp)[(size_t)node * 32 + lane] = a;
  } else {  // D == 16: two nodes per warp
    int node = (gt >> 5) * 2 + (lane >> 4);
    int l16 = lane & 15;
    if (node >= n) return;
    int j0 = g_rowptr[node], j1 = g_rowptr[node + 1];
    float a = z[(size_t)node * 16 + l16];
    float b = 0.f;
    int j = j0;
    for (; j + 1 < j1; j += 2) {
      int s0 = g_esrc[j], s1 = g_esrc[j + 1];
      a += g_wn[j] * h[(size_t)s0 * 16 + l16];
      b += g_wn[j + 1] * h[(size_t)s1 * 16 + l16];
    }
    if (j < j1) a += g_wn[j] * h[(size_t)g_esrc[j] * 16 + l16];
    a += b;
    if (EPI >= 1) a += bias[l16];
    outp[(size_t)node * 16 + l16] = a;
  }
}

// ---------------- launch ----------------
#define ID_Z  0
#define ID_H0 1
#define ID_H1 2
#define ID_T1 3
#define ID_T2 4

extern "C" void kernel_launch(void* const* d_in, const int* in_sizes, int n_in,
                              void* d_out, int out_size) {
  const float* x  = (const float*)d_in[0];
  const void*  ei = (const void*)d_in[1];
  const float* W1 = (const float*)d_in[2];
  const float* b1 = (const float*)d_in[3];
  const float* W2 = (const float*)d_in[4];
  const float* b2 = (const float*)d_in[5];
  const float* W3 = (const float*)d_in[6];
  const float* b3 = (const float*)d_in[7];
  float* out = (float*)d_out;

  const int n  = in_sizes[0] / 128;
  const int nE = in_sizes[1] / 2;

  uint32_t d1k0, d1k1, d2k0, d2k1;
  threefry2x32(0u, 42u, 0u, 0u, d1k0, d1k1);
  threefry2x32(0u, 42u, 0u, 1u, d2k0, d2k1);

  const int TB = 256;
  int gN   = (n + TB - 1) / TB;
  int gE   = (nE + TB - 1) / TB;
  int gW   = ((long long)n * 32 + TB - 1) / TB;
  int gW16 = (((n + 1) / 2) * 32 + TB - 1) / TB;
  int mT   = (n + 127) / 128;
  int nb   = (n + 1023) / 1024;
  size_t N = (size_t)n;

  // idx0..2: preprocessing front
  zero_detect_kernel<<<gN, TB>>>((const uint32_t*)ei, n);
  hist_kernel<<<gE, TB>>>(ei, nE, n);
  scan_partial_dis_kernel<<<nb, 1024>>>(n);
  // idx3: layer-1 GEMM (independent of graph preprocessing; profiling target)
  gemm_kernel<128, 128><<<dim3(mT, 8), 256>>>(x, -1, W1, n);
  // idx4..6: preprocessing tail
  scan_totals_kernel<<<1, 256>>>(nb);
  scan_add_kernel<<<gN, TB>>>(n);
  scatter_kernel<<<gE, TB>>>(ei, nE, n);

  // ---- layer 1 hops (D=128): u = A*u + z_k ----
  spmm_kernel<128, 0><<<gW, TB>>>(ID_Z, 3 * N * 128, 2 * N * 128, nullptr, ID_H0, nullptr, n, 0u, 0u);
  spmm_kernel<128, 0><<<gW, TB>>>(ID_H0, 0, 1 * N * 128, nullptr, ID_H1, nullptr, n, 0u, 0u);
  spmm_kernel<128, 1><<<gW, TB>>>(ID_H1, 0, 0, nullptr, ID_T1, b1, n, d1k0, d1k1);

  // ---- layer 2: GEMM then hops (D=64) ----
  gemm_kernel<128, 64><<<dim3(mT, 4), 256>>>(nullptr, ID_T1, W2, n);
  spmm_kernel<64, 0><<<gW, TB>>>(ID_Z, 3 * N * 64, 2 * N * 64, nullptr, ID_H0, nullptr, n, 0u, 0u);
  spmm_kernel<64, 0><<<gW, TB>>>(ID_H0, 0, 1 * N * 64, nullptr, ID_H1, nullptr, n, 0u, 0u);
  spmm_kernel<64, 2><<<gW, TB>>>(ID_H1, 0, 0, nullptr, ID_T2, b2, n, d2k0, d2k1);

  // ---- layer 3: GEMM then hops (D=16) ----
  gemm_kernel<64, 16><<<dim3(mT, 1), 256>>>(nullptr, ID_T2, W3, n);
  spmm_kernel<16, 0><<<gW16, TB>>>(ID_Z, 3 * N * 16, 2 * N * 16, nullptr, ID_H0, nullptr, n, 0u, 0u);
  spmm_kernel<16, 0><<<gW16, TB>>>(ID_H0, 0, 1 * N * 16, nullptr, ID_H1, nullptr, n, 0u, 0u);
  spmm_kernel<16, 3><<<gW16, TB>>>(ID_H1, 0, 0, out, -1, b3, n, 0u, 0u);
}

// round 15
// speedup vs baseline: 1.8033x; 1.3527x over previous
#include <cuda_runtime.h>
#include <stdint.h>

#define N_MAX 100000
#define E_MAX 1600000

typedef unsigned long long ull;

// ---------------- scratch (device globals; no allocation) ----------------
__device__ float g_z[N_MAX * 512];     // 4 compact hop buffers: z_k at k*n*DOUT
__device__ float g_h0[N_MAX * 128];
__device__ float g_h1[N_MAX * 128];
__device__ float g_t1[N_MAX * 128];
__device__ float g_t2[N_MAX * 64];
__device__ float g_dis[N_MAX];
__device__ float g_wn[E_MAX];
__device__ int   g_hist[N_MAX];
__device__ int   g_rowptr[N_MAX + 1];
__device__ int   g_cursor[N_MAX];
__device__ int   g_esrc[E_MAX];
__device__ int   g_is64;
__device__ int   g_bsum[256];
__device__ int   g_boff[256];
__device__ int   g_total;

// ids: 0=g_z 1=g_h0 2=g_h1 3=g_t1 4=g_t2
__device__ __forceinline__ float* bufp(int id) {
  switch (id) {
    case 0: return g_z;
    case 1: return g_h0;
    case 2: return g_h1;
    case 3: return g_t1;
    default: return g_t2;
  }
}

// ---------------- threefry2x32 (JAX-compatible) ----------------
__host__ __device__ static inline uint32_t rotl32(uint32_t v, int d) {
  return (v << d) | (v >> (32 - d));
}

__host__ __device__ static inline void threefry2x32(uint32_t k0, uint32_t k1,
                                                    uint32_t x0, uint32_t x1,
                                                    uint32_t& o0, uint32_t& o1) {
  uint32_t ks2 = k0 ^ k1 ^ 0x1BD11BDAu;
  x0 += k0; x1 += k1;
#define TF_R(r) { x0 += x1; x1 = rotl32(x1, (r)); x1 ^= x0; }
  TF_R(13) TF_R(15) TF_R(26) TF_R(6)
  x0 += k1; x1 += ks2 + 1u;
  TF_R(17) TF_R(29) TF_R(16) TF_R(24)
  x0 += ks2; x1 += k0 + 2u;
  TF_R(13) TF_R(15) TF_R(26) TF_R(6)
  x0 += k0; x1 += k1 + 3u;
  TF_R(17) TF_R(29) TF_R(16) TF_R(24)
  x0 += k1; x1 += ks2 + 4u;
  TF_R(13) TF_R(15) TF_R(26) TF_R(6)
  x0 += ks2; x1 += k0 + 5u;
#undef TF_R
  o0 = x0; o1 = x1;
}

__device__ __forceinline__ float drop_apply(float v, uint32_t k0, uint32_t k1, uint32_t idx) {
  uint32_t o0, o1;
  threefry2x32(k0, k1, 0u, idx, o0, o1);
  return ((o0 ^ o1) & 0x80000000u) ? 0.0f : 2.0f * v;
}

// ---------------- preprocessing kernels ----------------
__global__ void zero_detect_kernel(const uint32_t* __restrict__ eiw, int n) {
  int i = blockIdx.x * blockDim.x + threadIdx.x;
  if (i < n) g_hist[i] = 0;
  if (blockIdx.x == 0 && threadIdx.x == 0) {
    int all0 = 1;
    for (int k = 0; k < 64; k++)
      if (eiw[2 * k + 1] != 0u) { all0 = 0; break; }
    g_is64 = all0;
  }
}

__device__ __forceinline__ int edge_val(const void* ei, int nE, int idx) {
  if (g_is64) return (int)((const long long*)ei)[idx];
  return ((const int*)ei)[idx];
}

__global__ void hist_kernel(const void* __restrict__ ei, int nE, int n) {
  int e = blockIdx.x * blockDim.x + threadIdx.x;
  if (e < nE) {
    int c = edge_val(ei, nE, nE + e);
    if ((unsigned)c < (unsigned)n) atomicAdd(&g_hist[c], 1);
  }
}

__global__ void scan_partial_dis_kernel(int n) {
  __shared__ int wsum[32];
  int tid = threadIdx.x;
  int i = blockIdx.x * 1024 + tid;
  int v = (i < n) ? g_hist[i] : 0;
  if (i < n) g_dis[i] = (v > 0) ? rsqrtf((float)v) : 0.0f;
  int lane = tid & 31, wid = tid >> 5;
  int s = v;
#pragma unroll
  for (int off = 1; off < 32; off <<= 1) {
    int t = __shfl_up_sync(0xFFFFFFFFu, s, off);
    if (lane >= off) s += t;
  }
  if (lane == 31) wsum[wid] = s;
  __syncthreads();
  if (wid == 0) {
    int w = (lane < 32) ? wsum[lane] : 0;
#pragma unroll
    for (int off = 1; off < 32; off <<= 1) {
      int t = __shfl_up_sync(0xFFFFFFFFu, w, off);
      if (lane >= off) w += t;
    }
    wsum[lane] = w;
  }
  __syncthreads();
  int incl = s + (wid > 0 ? wsum[wid - 1] : 0);
  if (i < n) g_cursor[i] = incl;
  if (tid == 1023) g_bsum[blockIdx.x] = incl;
}

__global__ void scan_totals_kernel(int nb) {
  __shared__ int buf[256];
  int tid = threadIdx.x;
  int v = (tid < nb) ? g_bsum[tid] : 0;
  buf[tid] = v;
  __syncthreads();
#pragma unroll
  for (int off = 1; off < 256; off <<= 1) {
    int t = (tid >= off) ? buf[tid - off] : 0;
    __syncthreads();
    buf[tid] += t;
    __syncthreads();
  }
  if (tid < nb) g_boff[tid] = buf[tid] - v;
  if (tid == 255) g_total = buf[255];
}

__global__ void scan_add_kernel(int n) {
  int i = blockIdx.x * blockDim.x + threadIdx.x;
  if (i < n) {
    int excl = g_cursor[i] - g_hist[i] + g_boff[i >> 10];
    g_rowptr[i] = excl;
    g_cursor[i] = excl;
  }
  if (i == 0) g_rowptr[n] = g_total;
}

__global__ void scatter_kernel(const void* __restrict__ ei, int nE, int n) {
  int e = blockIdx.x * blockDim.x + threadIdx.x;
  if (e < nE) {
    int r = edge_val(ei, nE, e);
    int c = edge_val(ei, nE, nE + e);
    if ((unsigned)r < (unsigned)n && (unsigned)c < (unsigned)n) {
      int pos = atomicAdd(&g_cursor[c], 1);
      g_esrc[pos] = r;
      g_wn[pos] = g_dis[r] * g_dis[c];
    }
  }
}

// ---------------- GEMM: z_k[m][o] = sum_i X[m][i] * W[k*DOUT+o][i] ----------------
// TM=128, TN in {128,64}, TK=16, 256 threads, 8x(TN/16) microtile.
// Crossbar-balanced: row-pair accumulators (natural X pairs), W loaded as
// scalars and duplicated via mov.b64 on the ALU pipe -> 0.5 smem-B/FLOP.
#define FFMA2(acc, a, b) asm("fma.rn.f32x2 %0, %1, %2, %0;" : "+l"(acc) : "l"(a), "l"(b))
#define PACKDUP(out, f)  asm("mov.b64 %0, {%1, %1};" : "=l"(out) : "f"(f))

union F4U2 { float4 f4; ull u2[2]; float f[4]; };

template <int DIN, int DOUT, int TN>
__global__ __launch_bounds__(256, 2) void gemm_kernel(const float* __restrict__ Xext, int Xid,
                                                      const float* __restrict__ W, int n) {
  constexpr int TM = 128, TK = 16;
  constexpr int CPT = TN / 16;        // cols per thread: 8 (TN=128) or 4 (TN=64)
  __shared__ float XsT[TK][TM + 4];   // [kk][row]
  __shared__ float WsT[TK][TN + 4];   // [kk][col]  (no duplication)
  const float* X = Xext ? Xext : bufp(Xid);
  int t = threadIdx.x;
  int m0 = blockIdx.x * TM;
  int n0 = blockIdx.y * TN;
  int ty = t >> 4, tx = t & 15;
  int lrow = t >> 1;
  int lkb  = (t & 1) * 8;
  int mrow = m0 + lrow;
  // W loader geometry
  constexpr int WPT = TN * TK / 256;  // floats per thread: 8 or 4
  int wcol = (WPT == 8) ? (t >> 1) : (t >> 2);
  int wkb  = (WPT == 8) ? ((t & 1) * 8) : ((t & 3) * 4);

  ull acc[4][CPT];
#pragma unroll
  for (int i = 0; i < 4; i++)
#pragma unroll
    for (int j = 0; j < CPT; j++) acc[i][j] = 0ull;

  // prologue prefetch
  float4 xa, xb, wva, wvb;
  if (mrow < n) {
    const float4* xp = (const float4*)(X + (size_t)mrow * DIN + lkb);
    xa = xp[0]; xb = xp[1];
  } else {
    xa = make_float4(0.f, 0.f, 0.f, 0.f); xb = xa;
  }
  {
    const float* wp = W + (size_t)(n0 + wcol) * DIN + wkb;
    wva = *(const float4*)wp;
    if (WPT == 8) wvb = *(const float4*)(wp + 4);
  }

  for (int k0 = 0; k0 < DIN; k0 += TK) {
    __syncthreads();
    XsT[lkb + 0][lrow] = xa.x; XsT[lkb + 1][lrow] = xa.y;
    XsT[lkb + 2][lrow] = xa.z; XsT[lkb + 3][lrow] = xa.w;
    XsT[lkb + 4][lrow] = xb.x; XsT[lkb + 5][lrow] = xb.y;
    XsT[lkb + 6][lrow] = xb.z; XsT[lkb + 7][lrow] = xb.w;
    WsT[wkb + 0][wcol] = wva.x; WsT[wkb + 1][wcol] = wva.y;
    WsT[wkb + 2][wcol] = wva.z; WsT[wkb + 3][wcol] = wva.w;
    if (WPT == 8) {
      WsT[wkb + 4][wcol] = wvb.x; WsT[wkb + 5][wcol] = wvb.y;
      WsT[wkb + 6][wcol] = wvb.z; WsT[wkb + 7][wcol] = wvb.w;
    }
    __syncthreads();

    // prefetch next tile while computing this one
    int kn = k0 + TK;
    if (kn < DIN) {
      if (mrow < n) {
        const float4* xp = (const float4*)(X + (size_t)mrow * DIN + kn + lkb);
        xa = xp[0]; xb = xp[1];
      } else {
        xa = make_float4(0.f, 0.f, 0.f, 0.f); xb = xa;
      }
      const float* wp = W + (size_t)(n0 + wcol) * DIN + kn + wkb;
      wva = *(const float4*)wp;
      if (WPT == 8) wvb = *(const float4*)(wp + 4);
    }

#pragma unroll
    for (int kk = 0; kk < TK; kk++) {
      // X: 8 rows as 4 natural ull pairs
      F4U2 x0, x1;
      x0.f4 = *(const float4*)&XsT[kk][ty * 8];
      x1.f4 = *(const float4*)&XsT[kk][ty * 8 + 4];
      ull xr[4] = {x0.u2[0], x0.u2[1], x1.u2[0], x1.u2[1]};
      // W: CPT cols in halves of 4 to limit live duplicated regs
      F4U2 w0;
      w0.f4 = *(const float4*)&WsT[kk][tx * CPT];
      ull wd[4];
      PACKDUP(wd[0], w0.f[0]); PACKDUP(wd[1], w0.f[1]);
      PACKDUP(wd[2], w0.f[2]); PACKDUP(wd[3], w0.f[3]);
#pragma unroll
      for (int i = 0; i < 4; i++)
#pragma unroll
        for (int j = 0; j < 4; j++) FFMA2(acc[i][j], xr[i], wd[j]);
      if (CPT == 8) {
        F4U2 w1;
        w1.f4 = *(const float4*)&WsT[kk][tx * CPT + 4];
        ull we[4];
        PACKDUP(we[0], w1.f[0]); PACKDUP(we[1], w1.f[1]);
        PACKDUP(we[2], w1.f[2]); PACKDUP(we[3], w1.f[3]);
#pragma unroll
        for (int i = 0; i < 4; i++)
#pragma unroll
          for (int j = 0; j < 4; j++) FFMA2(acc[i][4 + j], xr[i], we[j]);
      }
    }
  }

  // epilogue: write to compact z_k buffer (thread's CPT cols stay in one hop)
  int colb = n0 + tx * CPT;
  int hop = colb / DOUT;
  int cib = colb - hop * DOUT;
  float* zb = g_z + (size_t)hop * n * DOUT;
#pragma unroll
  for (int ip = 0; ip < 4; ip++) {
#pragma unroll
    for (int hi = 0; hi < 2; hi++) {
      int r = m0 + ty * 8 + ip * 2 + hi;
      if (r < n) {
        float v[CPT];
#pragma unroll
        for (int j = 0; j < CPT; j++) {
          float2 p = *(const float2*)&acc[ip][j];
          v[j] = hi ? p.y : p.x;
        }
#pragma unroll
        for (int q = 0; q < CPT / 4; q++)
          *(float4*)(zb + (size_t)r * DOUT + cib + q * 4) =
              make_float4(v[q * 4], v[q * 4 + 1], v[q * 4 + 2], v[q * 4 + 3]);
      }
    }
  }
}

// ---------------- SpMM (Horner step): out = A*h + z (+bias,+elu,+dropout) ----------------
// EPI: 0 none; 1 bias+dropout; 2 bias+elu+dropout; 3 bias only
template <int D, int EPI>
__global__ void spmm_kernel(int hId, size_t hOff, size_t zOff,
                            float* __restrict__ outExt, int outId,
                            const float* __restrict__ bias, int n,
                            uint32_t k0, uint32_t k1) {
  int gt = blockIdx.x * blockDim.x + threadIdx.x;
  int lane = threadIdx.x & 31;
  const float* h = bufp(hId) + hOff;
  const float* z = g_z + zOff;
  float* outp = outExt ? outExt : bufp(outId);

  if (D == 128) {
    int node = gt >> 5;
    if (node >= n) return;
    int j0 = g_rowptr[node], j1 = g_rowptr[node + 1];
    const float4* h4 = (const float4*)h;
    float4 a = *(const float4*)(z + (size_t)node * 128 + lane * 4);
    float4 b = make_float4(0.f, 0.f, 0.f, 0.f);
    int j = j0;
    for (; j + 3 < j1; j += 4) {
      int s0 = g_esrc[j], s1 = g_esrc[j + 1], s2 = g_esrc[j + 2], s3 = g_esrc[j + 3];
      float w0 = g_wn[j], w1 = g_wn[j + 1], w2 = g_wn[j + 2], w3 = g_wn[j + 3];
      float4 v0 = h4[(size_t)s0 * 32 + lane];
      float4 v1 = h4[(size_t)s1 * 32 + lane];
      float4 v2 = h4[(size_t)s2 * 32 + lane];
      float4 v3 = h4[(size_t)s3 * 32 + lane];
      a.x += w0 * v0.x; a.y += w0 * v0.y; a.z += w0 * v0.z; a.w += w0 * v0.w;
      b.x += w1 * v1.x; b.y += w1 * v1.y; b.z += w1 * v1.z; b.w += w1 * v1.w;
      a.x += w2 * v2.x; a.y += w2 * v2.y; a.z += w2 * v2.z; a.w += w2 * v2.w;
      b.x += w3 * v3.x; b.y += w3 * v3.y; b.z += w3 * v3.z; b.w += w3 * v3.w;
    }
    for (; j < j1; j++) {
      int s = g_esrc[j]; float w = g_wn[j];
      float4 v = h4[(size_t)s * 32 + lane];
      a.x += w * v.x; a.y += w * v.y; a.z += w * v.z; a.w += w * v.w;
    }
    a.x += b.x; a.y += b.y; a.z += b.z; a.w += b.w;
    if (EPI >= 1) {
      float4 bb = ((const float4*)bias)[lane];
      a.x += bb.x; a.y += bb.y; a.z += bb.z; a.w += bb.w;
      if (EPI == 2) {
        a.x = (a.x > 0.f) ? a.x : expm1f(a.x);
        a.y = (a.y > 0.f) ? a.y : expm1f(a.y);
        a.z = (a.z > 0.f) ? a.z : expm1f(a.z);
        a.w = (a.w > 0.f) ? a.w : expm1f(a.w);
      }
      if (EPI <= 2) {
        uint32_t ib = (uint32_t)node * 128u + lane * 4u;
        a.x = drop_apply(a.x, k0, k1, ib + 0u);
        a.y = drop_apply(a.y, k0, k1, ib + 1u);
        a.z = drop_apply(a.z, k0, k1, ib + 2u);
        a.w = drop_apply(a.w, k0, k1, ib + 3u);
      }
    }
    ((float4*)outp)[(size_t)node * 32 + lane] = a;
  } else if (D == 64) {
    int node = gt >> 5;
    if (node >= n) return;
    int j0 = g_rowptr[node], j1 = g_rowptr[node + 1];
    const float2* h2 = (const float2*)h;
    float2 a = *(const float2*)(z + (size_t)node * 64 + lane * 2);
    float2 b = make_float2(0.f, 0.f);
    int j = j0;
    for (; j + 3 < j1; j += 4) {
      int s0 = g_esrc[j], s1 = g_esrc[j + 1], s2 = g_esrc[j + 2], s3 = g_esrc[j + 3];
      float w0 = g_wn[j], w1 = g_wn[j + 1], w2 = g_wn[j + 2], w3 = g_wn[j + 3];
      float2 v0 = h2[(size_t)s0 * 32 + lane];
      float2 v1 = h2[(size_t)s1 * 32 + lane];
      float2 v2 = h2[(size_t)s2 * 32 + lane];
      float2 v3 = h2[(size_t)s3 * 32 + lane];
      a.x += w0 * v0.x; a.y += w0 * v0.y;
      b.x += w1 * v1.x; b.y += w1 * v1.y;
      a.x += w2 * v2.x; a.y += w2 * v2.y;
      b.x += w3 * v3.x; b.y += w3 * v3.y;
    }
    for (; j < j1; j++) {
      int s = g_esrc[j]; float w = g_wn[j];
      float2 v = h2[(size_t)s * 32 + lane];
      a.x += w * v.x; a.y += w * v.y;
    }
    a.x += b.x; a.y += b.y;
    if (EPI >= 1) {
      float2 bb = ((const float2*)bias)[lane];
      a.x += bb.x; a.y += bb.y;
      if (EPI == 2) {
        a.x = (a.x > 0.f) ? a.x : expm1f(a.x);
        a.y = (a.y > 0.f) ? a.y : expm1f(a.y);
      }
      if (EPI <= 2) {
        uint32_t ib = (uint32_t)node * 64u + lane * 2u;
        a.x = drop_apply(a.x, k0, k1, ib + 0u);
        a.y = drop_apply(a.y, k0, k1, ib + 1u);
      }
    }
    ((float2*)outp)[(size_t)node * 32 + lane] = a;
  } else {  // D == 16: two nodes per warp
    int node = (gt >> 5) * 2 + (lane >> 4);
    int l16 = lane & 15;
    if (node >= n) return;
    int j0 = g_rowptr[node], j1 = g_rowptr[node + 1];
    float a = z[(size_t)node * 16 + l16];
    float b = 0.f;
    int j = j0;
    for (; j + 1 < j1; j += 2) {
      int s0 = g_esrc[j], s1 = g_esrc[j + 1];
      a += g_wn[j] * h[(size_t)s0 * 16 + l16];
      b += g_wn[j + 1] * h[(size_t)s1 * 16 + l16];
    }
    if (j < j1) a += g_wn[j] * h[(size_t)g_esrc[j] * 16 + l16];
    a += b;
    if (EPI >= 1) a += bias[l16];
    outp[(size_t)node * 16 + l16] = a;
  }
}

// ---------------- launch ----------------
#define ID_Z  0
#define ID_H0 1
#define ID_H1 2
#define ID_T1 3
#define ID_T2 4

extern "C" void kernel_launch(void* const* d_in, const int* in_sizes, int n_in,
                              void* d_out, int out_size) {
  const float* x  = (const float*)d_in[0];
  const void*  ei = (const void*)d_in[1];
  const float* W1 = (const float*)d_in[2];
  const float* b1 = (const float*)d_in[3];
  const float* W2 = (const float*)d_in[4];
  const float* b2 = (const float*)d_in[5];
  const float* W3 = (const float*)d_in[6];
  const float* b3 = (const float*)d_in[7];
  float* out = (float*)d_out;

  const int n  = in_sizes[0] / 128;
  const int nE = in_sizes[1] / 2;

  uint32_t d1k0, d1k1, d2k0, d2k1;
  threefry2x32(0u, 42u, 0u, 0u, d1k0, d1k1);
  threefry2x32(0u, 42u, 0u, 1u, d2k0, d2k1);

  const int TB = 256;
  int gN   = (n + TB - 1) / TB;
  int gE   = (nE + TB - 1) / TB;
  int gW   = ((long long)n * 32 + TB - 1) / TB;
  int gW16 = (((n + 1) / 2) * 32 + TB - 1) / TB;
  int mT   = (n + 127) / 128;
  int nb   = (n + 1023) / 1024;
  size_t N = (size_t)n;

  // idx0..2: preprocessing front
  zero_detect_kernel<<<gN, TB>>>((const uint32_t*)ei, n);
  hist_kernel<<<gE, TB>>>(ei, nE, n);
  scan_partial_dis_kernel<<<nb, 1024>>>(n);
  // idx3: layer-1 GEMM (profiling target)
  gemm_kernel<128, 128, 128><<<dim3(mT, 4), 256>>>(x, -1, W1, n);
  // idx4..6: preprocessing tail
  scan_totals_kernel<<<1, 256>>>(nb);
  scan_add_kernel<<<gN, TB>>>(n);
  scatter_kernel<<<gE, TB>>>(ei, nE, n);

  // ---- layer 1 hops (D=128): u = A*u + z_k ----
  spmm_kernel<128, 0><<<gW, TB>>>(ID_Z, 3 * N * 128, 2 * N * 128, nullptr, ID_H0, nullptr, n, 0u, 0u);
  spmm_kernel<128, 0><<<gW, TB>>>(ID_H0, 0, 1 * N * 128, nullptr, ID_H1, nullptr, n, 0u, 0u);
  spmm_kernel<128, 1><<<gW, TB>>>(ID_H1, 0, 0, nullptr, ID_T1, b1, n, d1k0, d1k1);

  // ---- layer 2: GEMM then hops (D=64) ----
  gemm_kernel<128, 64, 128><<<dim3(mT, 2), 256>>>(nullptr, ID_T1, W2, n);
  spmm_kernel<64, 0><<<gW, TB>>>(ID_Z, 3 * N * 64, 2 * N * 64, nullptr, ID_H0, nullptr, n, 0u, 0u);
  spmm_kernel<64, 0><<<gW, TB>>>(ID_H0, 0, 1 * N * 64, nullptr, ID_H1, nullptr, n, 0u, 0u);
  spmm_kernel<64, 2><<<gW, TB>>>(ID_H1, 0, 0, nullptr, ID_T2, b2, n, d2k0, d2k1);

  // ---- layer 3: GEMM then hops (D=16) ----
  gemm_kernel<64, 16, 64><<<dim3(mT, 1), 256>>>(nullptr, ID_T2, W3, n);
  spmm_kernel<16, 0><<<gW16, TB>>>(ID_Z, 3 * N * 16, 2 * N * 16, nullptr, ID_H0, nullptr, n, 0u, 0u);
  spmm_kernel<16, 0><<<gW16, TB>>>(ID_H0, 0, 1 * N * 16, nullptr, ID_H1, nullptr, n, 0u, 0u);
  spmm_kernel<16, 3><<<gW16, TB>>>(ID_H1, 0, 0, out, -1, b3, n, 0u, 0u);
}

// round 16
// speedup vs baseline: 1.9739x; 1.0946x over previous
#include <cuda_runtime.h>
#include <stdint.h>

#define N_MAX 100000
#define E_MAX 1600000

typedef unsigned long long ull;

// ---------------- scratch (device globals; no allocation) ----------------
__device__ float g_z[N_MAX * 512];     // 4 compact hop buffers: z_k at k*n*DOUT
__device__ float g_h0[N_MAX * 128];
__device__ float g_h1[N_MAX * 128];
__device__ float g_t1[N_MAX * 128];
__device__ float g_t2[N_MAX * 64];
__device__ float g_dis[N_MAX];
__device__ float g_wn[E_MAX];
__device__ int   g_hist[N_MAX];
__device__ int   g_rowptr[N_MAX + 1];
__device__ int   g_cursor[N_MAX];
__device__ int   g_esrc[E_MAX];
__device__ int   g_is64;
__device__ int   g_bsum[256];
__device__ int   g_boff[256];
__device__ int   g_total;

// ids: 0=g_z 1=g_h0 2=g_h1 3=g_t1 4=g_t2
__device__ __forceinline__ float* bufp(int id) {
  switch (id) {
    case 0: return g_z;
    case 1: return g_h0;
    case 2: return g_h1;
    case 3: return g_t1;
    default: return g_t2;
  }
}

// ---------------- threefry2x32 (JAX-compatible) ----------------
__host__ __device__ static inline uint32_t rotl32(uint32_t v, int d) {
  return (v << d) | (v >> (32 - d));
}

__host__ __device__ static inline void threefry2x32(uint32_t k0, uint32_t k1,
                                                    uint32_t x0, uint32_t x1,
                                                    uint32_t& o0, uint32_t& o1) {
  uint32_t ks2 = k0 ^ k1 ^ 0x1BD11BDAu;
  x0 += k0; x1 += k1;
#define TF_R(r) { x0 += x1; x1 = rotl32(x1, (r)); x1 ^= x0; }
  TF_R(13) TF_R(15) TF_R(26) TF_R(6)
  x0 += k1; x1 += ks2 + 1u;
  TF_R(17) TF_R(29) TF_R(16) TF_R(24)
  x0 += ks2; x1 += k0 + 2u;
  TF_R(13) TF_R(15) TF_R(26) TF_R(6)
  x0 += k0; x1 += k1 + 3u;
  TF_R(17) TF_R(29) TF_R(16) TF_R(24)
  x0 += k1; x1 += ks2 + 4u;
  TF_R(13) TF_R(15) TF_R(26) TF_R(6)
  x0 += ks2; x1 += k0 + 5u;
#undef TF_R
  o0 = x0; o1 = x1;
}

__device__ __forceinline__ float drop_apply(float v, uint32_t k0, uint32_t k1, uint32_t idx) {
  uint32_t o0, o1;
  threefry2x32(k0, k1, 0u, idx, o0, o1);
  return ((o0 ^ o1) & 0x80000000u) ? 0.0f : 2.0f * v;
}

// ---------------- preprocessing kernels ----------------
__global__ void zero_detect_kernel(const uint32_t* __restrict__ eiw, int n) {
  int i = blockIdx.x * blockDim.x + threadIdx.x;
  if (i < n) g_hist[i] = 0;
  if (blockIdx.x == 0 && threadIdx.x == 0) {
    int all0 = 1;
    for (int k = 0; k < 64; k++)
      if (eiw[2 * k + 1] != 0u) { all0 = 0; break; }
    g_is64 = all0;
  }
}

__device__ __forceinline__ int edge_val(const void* ei, int nE, int idx) {
  if (g_is64) return (int)((const long long*)ei)[idx];
  return ((const int*)ei)[idx];
}

__global__ void hist_kernel(const void* __restrict__ ei, int nE, int n) {
  int e = blockIdx.x * blockDim.x + threadIdx.x;
  if (e < nE) {
    int c = edge_val(ei, nE, nE + e);
    if ((unsigned)c < (unsigned)n) atomicAdd(&g_hist[c], 1);
  }
}

__global__ void scan_partial_dis_kernel(int n) {
  __shared__ int wsum[32];
  int tid = threadIdx.x;
  int i = blockIdx.x * 1024 + tid;
  int v = (i < n) ? g_hist[i] : 0;
  if (i < n) g_dis[i] = (v > 0) ? rsqrtf((float)v) : 0.0f;
  int lane = tid & 31, wid = tid >> 5;
  int s = v;
#pragma unroll
  for (int off = 1; off < 32; off <<= 1) {
    int t = __shfl_up_sync(0xFFFFFFFFu, s, off);
    if (lane >= off) s += t;
  }
  if (lane == 31) wsum[wid] = s;
  __syncthreads();
  if (wid == 0) {
    int w = (lane < 32) ? wsum[lane] : 0;
#pragma unroll
    for (int off = 1; off < 32; off <<= 1) {
      int t = __shfl_up_sync(0xFFFFFFFFu, w, off);
      if (lane >= off) w += t;
    }
    wsum[lane] = w;
  }
  __syncthreads();
  int incl = s + (wid > 0 ? wsum[wid - 1] : 0);
  if (i < n) g_cursor[i] = incl;
  if (tid == 1023) g_bsum[blockIdx.x] = incl;
}

__global__ void scan_totals_kernel(int nb) {
  __shared__ int buf[256];
  int tid = threadIdx.x;
  int v = (tid < nb) ? g_bsum[tid] : 0;
  buf[tid] = v;
  __syncthreads();
#pragma unroll
  for (int off = 1; off < 256; off <<= 1) {
    int t = (tid >= off) ? buf[tid - off] : 0;
    __syncthreads();
    buf[tid] += t;
    __syncthreads();
  }
  if (tid < nb) g_boff[tid] = buf[tid] - v;
  if (tid == 255) g_total = buf[255];
}

__global__ void scan_add_kernel(int n) {
  int i = blockIdx.x * blockDim.x + threadIdx.x;
  if (i < n) {
    int excl = g_cursor[i] - g_hist[i] + g_boff[i >> 10];
    g_rowptr[i] = excl;
    g_cursor[i] = excl;
  }
  if (i == 0) g_rowptr[n] = g_total;
}

__global__ void scatter_kernel(const void* __restrict__ ei, int nE, int n) {
  int e = blockIdx.x * blockDim.x + threadIdx.x;
  if (e < nE) {
    int r = edge_val(ei, nE, e);
    int c = edge_val(ei, nE, nE + e);
    if ((unsigned)r < (unsigned)n && (unsigned)c < (unsigned)n) {
      int pos = atomicAdd(&g_cursor[c], 1);
      g_esrc[pos] = r;
      g_wn[pos] = g_dis[r] * g_dis[c];
    }
  }
}

// ---------------- GEMM: z_k[m][o] = sum_i X[m][i] * W[k*DOUT+o][i] ----------------
// TM=128, TN in {128,64}, TK=16, 256 threads, 8x(TN/16) microtile.
// Crossbar-balanced and bank-conflict-free: W read in two 4-col groups at
// 16B lane stride (contiguous 128B per LDS.128 phase); W duplicated to packed
// operands via mov.b64 on the ALU pipe.
#define FFMA2(acc, a, b) asm("fma.rn.f32x2 %0, %1, %2, %0;" : "+l"(acc) : "l"(a), "l"(b))
#define PACKDUP(out, f)  asm("mov.b64 %0, {%1, %1};" : "=l"(out) : "f"(f))

union F4U2 { float4 f4; ull u2[2]; float f[4]; };

template <int DIN, int DOUT, int TN>
__global__ __launch_bounds__(256, 2) void gemm_kernel(const float* __restrict__ Xext, int Xid,
                                                      const float* __restrict__ W, int n) {
  constexpr int TM = 128, TK = 16;
  constexpr int CPT = TN / 16;        // cols per thread: 8 (TN=128) or 4 (TN=64)
  constexpr int NG  = CPT / 4;        // column groups of 4
  __shared__ float XsT[TK][TM + 4];   // [kk][row]
  __shared__ float WsT[TK][TN + 4];   // [kk][col]
  const float* X = Xext ? Xext : bufp(Xid);
  int t = threadIdx.x;
  int m0 = blockIdx.x * TM;
  int n0 = blockIdx.y * TN;
  int ty = t >> 4, tx = t & 15;
  int lrow = t >> 1;
  int lkb  = (t & 1) * 8;
  int mrow = m0 + lrow;
  // W loader geometry
  constexpr int WPT = TN * TK / 256;  // floats per thread: 8 or 4
  int wcol = (WPT == 8) ? (t >> 1) : (t >> 2);
  int wkb  = (WPT == 8) ? ((t & 1) * 8) : ((t & 3) * 4);

  ull acc[4][CPT];
#pragma unroll
  for (int i = 0; i < 4; i++)
#pragma unroll
    for (int j = 0; j < CPT; j++) acc[i][j] = 0ull;

  // prologue prefetch
  float4 xa, xb, wva, wvb;
  if (mrow < n) {
    const float4* xp = (const float4*)(X + (size_t)mrow * DIN + lkb);
    xa = xp[0]; xb = xp[1];
  } else {
    xa = make_float4(0.f, 0.f, 0.f, 0.f); xb = xa;
  }
  {
    const float* wp = W + (size_t)(n0 + wcol) * DIN + wkb;
    wva = *(const float4*)wp;
    if (WPT == 8) wvb = *(const float4*)(wp + 4);
  }

  for (int k0 = 0; k0 < DIN; k0 += TK) {
    __syncthreads();
    XsT[lkb + 0][lrow] = xa.x; XsT[lkb + 1][lrow] = xa.y;
    XsT[lkb + 2][lrow] = xa.z; XsT[lkb + 3][lrow] = xa.w;
    XsT[lkb + 4][lrow] = xb.x; XsT[lkb + 5][lrow] = xb.y;
    XsT[lkb + 6][lrow] = xb.z; XsT[lkb + 7][lrow] = xb.w;
    WsT[wkb + 0][wcol] = wva.x; WsT[wkb + 1][wcol] = wva.y;
    WsT[wkb + 2][wcol] = wva.z; WsT[wkb + 3][wcol] = wva.w;
    if (WPT == 8) {
      WsT[wkb + 4][wcol] = wvb.x; WsT[wkb + 5][wcol] = wvb.y;
      WsT[wkb + 6][wcol] = wvb.z; WsT[wkb + 7][wcol] = wvb.w;
    }
    __syncthreads();

    // prefetch next tile while computing this one
    int kn = k0 + TK;
    if (kn < DIN) {
      if (mrow < n) {
        const float4* xp = (const float4*)(X + (size_t)mrow * DIN + kn + lkb);
        xa = xp[0]; xb = xp[1];
      } else {
        xa = make_float4(0.f, 0.f, 0.f, 0.f); xb = xa;
      }
      const float* wp = W + (size_t)(n0 + wcol) * DIN + kn + wkb;
      wva = *(const float4*)wp;
      if (WPT == 8) wvb = *(const float4*)(wp + 4);
    }

#pragma unroll
    for (int kk = 0; kk < TK; kk++) {
      // X: 8 rows as 4 natural ull pairs (quarter-warp broadcast, conflict-free)
      F4U2 x0, x1;
      x0.f4 = *(const float4*)&XsT[kk][ty * 8];
      x1.f4 = *(const float4*)&XsT[kk][ty * 8 + 4];
      ull xr[4] = {x0.u2[0], x0.u2[1], x1.u2[0], x1.u2[1]};
      // W group 0: cols tx*4..+3 (16B lane stride -> conflict-free)
      F4U2 w0;
      w0.f4 = *(const float4*)&WsT[kk][tx * 4];
      ull wd[4];
      PACKDUP(wd[0], w0.f[0]); PACKDUP(wd[1], w0.f[1]);
      PACKDUP(wd[2], w0.f[2]); PACKDUP(wd[3], w0.f[3]);
#pragma unroll
      for (int i = 0; i < 4; i++)
#pragma unroll
        for (int j = 0; j < 4; j++) FFMA2(acc[i][j], xr[i], wd[j]);
      if (NG == 2) {
        // W group 1: cols 64+tx*4..+3
        F4U2 w1;
        w1.f4 = *(const float4*)&WsT[kk][64 + tx * 4];
        ull we[4];
        PACKDUP(we[0], w1.f[0]); PACKDUP(we[1], w1.f[1]);
        PACKDUP(we[2], w1.f[2]); PACKDUP(we[3], w1.f[3]);
#pragma unroll
        for (int i = 0; i < 4; i++)
#pragma unroll
          for (int j = 0; j < 4; j++) FFMA2(acc[i][4 + j], xr[i], we[j]);
      }
    }
  }

  // epilogue: each 4-col group lies in one 64-aligned band -> one hop buffer
#pragma unroll
  for (int g = 0; g < NG; g++) {
    int colg = n0 + g * 64 + tx * 4;
    int hop = colg / DOUT;
    int cib = colg - hop * DOUT;
    float* zb = g_z + (size_t)hop * n * DOUT;
#pragma unroll
    for (int ip = 0; ip < 4; ip++) {
#pragma unroll
      for (int hi = 0; hi < 2; hi++) {
        int r = m0 + ty * 8 + ip * 2 + hi;
        if (r < n) {
          float2 p0 = *(const float2*)&acc[ip][g * 4 + 0];
          float2 p1 = *(const float2*)&acc[ip][g * 4 + 1];
          float2 p2 = *(const float2*)&acc[ip][g * 4 + 2];
          float2 p3 = *(const float2*)&acc[ip][g * 4 + 3];
          float4 v = hi ? make_float4(p0.y, p1.y, p2.y, p3.y)
                        : make_float4(p0.x, p1.x, p2.x, p3.x);
          *(float4*)(zb + (size_t)r * DOUT + cib) = v;
        }
      }
    }
  }
}

// ---------------- SpMM (Horner step): out = A*h + z (+bias,+elu,+dropout) ----------------
// EPI: 0 none; 1 bias+dropout; 2 bias+elu+dropout; 3 bias only
template <int D, int EPI>
__global__ void spmm_kernel(int hId, size_t hOff, size_t zOff,
                            float* __restrict__ outExt, int outId,
                            const float* __restrict__ bias, int n,
                            uint32_t k0, uint32_t k1) {
  int gt = blockIdx.x * blockDim.x + threadIdx.x;
  int lane = threadIdx.x & 31;
  const float* h = bufp(hId) + hOff;
  const float* z = g_z + zOff;
  float* outp = outExt ? outExt : bufp(outId);

  if (D == 128) {
    int node = gt >> 5;
    if (node >= n) return;
    int j0 = g_rowptr[node], j1 = g_rowptr[node + 1];
    const float4* h4 = (const float4*)h;
    float4 a = *(const float4*)(z + (size_t)node * 128 + lane * 4);
    float4 b = make_float4(0.f, 0.f, 0.f, 0.f);
    int j = j0;
    for (; j + 3 < j1; j += 4) {
      int s0 = g_esrc[j], s1 = g_esrc[j + 1], s2 = g_esrc[j + 2], s3 = g_esrc[j + 3];
      float w0 = g_wn[j], w1 = g_wn[j + 1], w2 = g_wn[j + 2], w3 = g_wn[j + 3];
      float4 v0 = h4[(size_t)s0 * 32 + lane];
      float4 v1 = h4[(size_t)s1 * 32 + lane];
      float4 v2 = h4[(size_t)s2 * 32 + lane];
      float4 v3 = h4[(size_t)s3 * 32 + lane];
      a.x += w0 * v0.x; a.y += w0 * v0.y; a.z += w0 * v0.z; a.w += w0 * v0.w;
      b.x += w1 * v1.x; b.y += w1 * v1.y; b.z += w1 * v1.z; b.w += w1 * v1.w;
      a.x += w2 * v2.x; a.y += w2 * v2.y; a.z += w2 * v2.z; a.w += w2 * v2.w;
      b.x += w3 * v3.x; b.y += w3 * v3.y; b.z += w3 * v3.z; b.w += w3 * v3.w;
    }
    for (; j < j1; j++) {
      int s = g_esrc[j]; float w = g_wn[j];
      float4 v = h4[(size_t)s * 32 + lane];
      a.x += w * v.x; a.y += w * v.y; a.z += w * v.z; a.w += w * v.w;
    }
    a.x += b.x; a.y += b.y; a.z += b.z; a.w += b.w;
    if (EPI >= 1) {
      float4 bb = ((const float4*)bias)[lane];
      a.x += bb.x; a.y += bb.y; a.z += bb.z; a.w += bb.w;
      if (EPI == 2) {
        a.x = (a.x > 0.f) ? a.x : expm1f(a.x);
        a.y = (a.y > 0.f) ? a.y : expm1f(a.y);
        a.z = (a.z > 0.f) ? a.z : expm1f(a.z);
        a.w = (a.w > 0.f) ? a.w : expm1f(a.w);
      }
      if (EPI <= 2) {
        uint32_t ib = (uint32_t)node * 128u + lane * 4u;
        a.x = drop_apply(a.x, k0, k1, ib + 0u);
        a.y = drop_apply(a.y, k0, k1, ib + 1u);
        a.z = drop_apply(a.z, k0, k1, ib + 2u);
        a.w = drop_apply(a.w, k0, k1, ib + 3u);
      }
    }
    ((float4*)outp)[(size_t)node * 32 + lane] = a;
  } else if (D == 64) {
    int node = gt >> 5;
    if (node >= n) return;
    int j0 = g_rowptr[node], j1 = g_rowptr[node + 1];
    const float2* h2 = (const float2*)h;
    float2 a = *(const float2*)(z + (size_t)node * 64 + lane * 2);
    float2 b = make_float2(0.f, 0.f);
    int j = j0;
    for (; j + 3 < j1; j += 4) {
      int s0 = g_esrc[j], s1 = g_esrc[j + 1], s2 = g_esrc[j + 2], s3 = g_esrc[j + 3];
      float w0 = g_wn[j], w1 = g_wn[j + 1], w2 = g_wn[j + 2], w3 = g_wn[j + 3];
      float2 v0 = h2[(size_t)s0 * 32 + lane];
      float2 v1 = h2[(size_t)s1 * 32 + lane];
      float2 v2 = h2[(size_t)s2 * 32 + lane];
      float2 v3 = h2[(size_t)s3 * 32 + lane];
      a.x += w0 * v0.x; a.y += w0 * v0.y;
      b.x += w1 * v1.x; b.y += w1 * v1.y;
      a.x += w2 * v2.x; a.y += w2 * v2.y;
      b.x += w3 * v3.x; b.y += w3 * v3.y;
    }
    for (; j < j1; j++) {
      int s = g_esrc[j]; float w = g_wn[j];
      float2 v = h2[(size_t)s * 32 + lane];
      a.x += w * v.x; a.y += w * v.y;
    }
    a.x += b.x; a.y += b.y;
    if (EPI >= 1) {
      float2 bb = ((const float2*)bias)[lane];
      a.x += bb.x; a.y += bb.y;
      if (EPI == 2) {
        a.x = (a.x > 0.f) ? a.x : expm1f(a.x);
        a.y = (a.y > 0.f) ? a.y : expm1f(a.y);
      }
      if (EPI <= 2) {
        uint32_t ib = (uint32_t)node * 64u + lane * 2u;
        a.x = drop_apply(a.x, k0, k1, ib + 0u);
        a.y = drop_apply(a.y, k0, k1, ib + 1u);
      }
    }
    ((float2*)outp)[(size_t)node * 32 + lane] = a;
  } else {  // D == 16: two nodes per warp
    int node = (gt >> 5) * 2 + (lane >> 4);
    int l16 = lane & 15;
    if (node >= n) return;
    int j0 = g_rowptr[node], j1 = g_rowptr[node + 1];
    float a = z[(size_t)node * 16 + l16];
    float b = 0.f;
    int j = j0;
    for (; j + 1 < j1; j += 2) {
      int s0 = g_esrc[j], s1 = g_esrc[j + 1];
      a += g_wn[j] * h[(size_t)s0 * 16 + l16];
      b += g_wn[j + 1] * h[(size_t)s1 * 16 + l16];
    }
    if (j < j1) a += g_wn[j] * h[(size_t)g_esrc[j] * 16 + l16];
    a += b;
    if (EPI >= 1) a += bias[l16];
    outp[(size_t)node * 16 + l16] = a;
  }
}

// ---------------- launch ----------------
#define ID_Z  0
#define ID_H0 1
#define ID_H1 2
#define ID_T1 3
#define ID_T2 4

extern "C" void kernel_launch(void* const* d_in, const int* in_sizes, int n_in,
                              void* d_out, int out_size) {
  const float* x  = (const float*)d_in[0];
  const void*  ei = (const void*)d_in[1];
  const float* W1 = (const float*)d_in[2];
  const float* b1 = (const float*)d_in[3];
  const float* W2 = (const float*)d_in[4];
  const float* b2 = (const float*)d_in[5];
  const float* W3 = (const float*)d_in[6];
  const float* b3 = (const float*)d_in[7];
  float* out = (float*)d_out;

  const int n  = in_sizes[0] / 128;
  const int nE = in_sizes[1] / 2;

  uint32_t d1k0, d1k1, d2k0, d2k1;
  threefry2x32(0u, 42u, 0u, 0u, d1k0, d1k1);
  threefry2x32(0u, 42u, 0u, 1u, d2k0, d2k1);

  const int TB = 256;
  int gN   = (n + TB - 1) / TB;
  int gE   = (nE + TB - 1) / TB;
  int gW   = ((long long)n * 32 + TB - 1) / TB;
  int gW16 = (((n + 1) / 2) * 32 + TB - 1) / TB;
  int mT   = (n + 127) / 128;
  int nb   = (n + 1023) / 1024;
  size_t N = (size_t)n;

  // idx0..2: preprocessing front
  zero_detect_kernel<<<gN, TB>>>((const uint32_t*)ei, n);
  hist_kernel<<<gE, TB>>>(ei, nE, n);
  scan_partial_dis_kernel<<<nb, 1024>>>(n);
  // idx3: layer-1 GEMM (profiling target)
  gemm_kernel<128, 128, 128><<<dim3(mT, 4), 256>>>(x, -1, W1, n);
  // idx4..6: preprocessing tail
  scan_totals_kernel<<<1, 256>>>(nb);
  scan_add_kernel<<<gN, TB>>>(n);
  scatter_kernel<<<gE, TB>>>(ei, nE, n);

  // ---- layer 1 hops (D=128): u = A*u + z_k ----
  spmm_kernel<128, 0><<<gW, TB>>>(ID_Z, 3 * N * 128, 2 * N * 128, nullptr, ID_H0, nullptr, n, 0u, 0u);
  spmm_kernel<128, 0><<<gW, TB>>>(ID_H0, 0, 1 * N * 128, nullptr, ID_H1, nullptr, n, 0u, 0u);
  spmm_kernel<128, 1><<<gW, TB>>>(ID_H1, 0, 0, nullptr, ID_T1, b1, n, d1k0, d1k1);

  // ---- layer 2: GEMM then hops (D=64) ----
  gemm_kernel<128, 64, 128><<<dim3(mT, 2), 256>>>(nullptr, ID_T1, W2, n);
  spmm_kernel<64, 0><<<gW, TB>>>(ID_Z, 3 * N * 64, 2 * N * 64, nullptr, ID_H0, nullptr, n, 0u, 0u);
  spmm_kernel<64, 0><<<gW, TB>>>(ID_H0, 0, 1 * N * 64, nullptr, ID_H1, nullptr, n, 0u, 0u);
  spmm_kernel<64, 2><<<gW, TB>>>(ID_H1, 0, 0, nullptr, ID_T2, b2, n, d2k0, d2k1);

  // ---- layer 3: GEMM then hops (D=16) ----
  gemm_kernel<64, 16, 64><<<dim3(mT, 1), 256>>>(nullptr, ID_T2, W3, n);
  spmm_kernel<16, 0><<<gW16, TB>>>(ID_Z, 3 * N * 16, 2 * N * 16, nullptr, ID_H0, nullptr, n, 0u, 0u);
  spmm_kernel<16, 0><<<gW16, TB>>>(ID_H0, 0, 1 * N * 16, nullptr, ID_H1, nullptr, n, 0u, 0u);
  spmm_kernel<16, 3><<<gW16, TB>>>(ID_H1, 0, 0, out, -1, b3, n, 0u, 0u);
}